// round 11
// baseline (speedup 1.0000x reference)
#include <cuda_runtime.h>
#include <cuda_bf16.h>
#include <math.h>

#define T_ 256
#define B_ 16
#define E_ 512
#define H_ 2048
#define N_ 14839
#define U_ 48
#define G4H 8192
#define EPS_ 1e-6f
#define NT 256
#define GRID 256
#define LMROWS 310            /* lm rows per step chunk: 48*310 = 14880 >= N */

/* ---------------- scratch ---------------- */
__device__ float g_xh_m[T_*B_*E_];
__device__ float g_xh_c[T_*B_*E_];
__device__ float g_emb[U_*B_*E_];
__device__ float g_eg[(size_t)U_*B_*G4H];
__device__ float g_gates[(size_t)B_*G4H];
__device__ float g_h[2][B_*H_];
__device__ float g_c[2][B_*H_];
__device__ float g_alpha[2][T_*B_];
__device__ float g_sm[B_*E_];
__device__ float g_sc[B_*E_];
__device__ float g_p[T_*B_];
__device__ float g_u[T_*B_];
__device__ float g_scall[U_*B_*2*E_];
__device__ float g_wpT[H_*E_];
__device__ float g_comb[2*E_*H_];
__device__ __nv_bfloat16 g_whh_bf[(size_t)G4H*H_];
__device__ __nv_bfloat16 g_wihc_bf[(size_t)G4H*E_];
__device__ __nv_bfloat16 g_hbf[B_*H_];
__device__ __nv_bfloat16 g_ctxbf[B_*E_];

/* grid barrier state */
__device__ unsigned g_cnt = 0;
__device__ volatile unsigned g_gen = 0;

__device__ __forceinline__ void gbar() {
    __syncthreads();
    if (threadIdx.x == 0) {
        unsigned gen = g_gen;
        __threadfence();
        if (atomicAdd(&g_cnt, 1u) == gridDim.x - 1u) {
            g_cnt = 0;
            __threadfence();
            g_gen = gen + 1u;
        } else {
            while (g_gen == gen) __nanosleep(32);
        }
        __threadfence();
    }
    __syncthreads();
}

__device__ __forceinline__ float sigm(float x) { return 1.f / (1.f + expf(-x)); }
__device__ __forceinline__ float tanha(float x) {
    float y; asm("tanh.approx.f32 %0, %1;" : "=f"(y) : "f"(x)); return y;
}
__device__ __forceinline__ void bf8(float4 raw, float* o) {
    const __nv_bfloat162* p = (const __nv_bfloat162*)&raw;
    float2 a = __bfloat1622float2(p[0]); float2 b = __bfloat1622float2(p[1]);
    float2 c = __bfloat1622float2(p[2]); float2 d = __bfloat1622float2(p[3]);
    o[0]=a.x;o[1]=a.y;o[2]=b.x;o[3]=b.y;o[4]=c.x;o[5]=c.y;o[6]=d.x;o[7]=d.y;
}
__device__ __forceinline__ unsigned tf32c(float x) {
    unsigned r; asm("cvt.rna.tf32.f32 %0, %1;" : "=r"(r) : "f"(x)); return r;
}

/* ---------------- init ---------------- */
__global__ void init_state(float* h, float* c, float* alpha,
                           __nv_bfloat16* hbf, __nv_bfloat16* ctxbf) {
    int i = blockIdx.x * blockDim.x + threadIdx.x;
    if (i < 2*B_*H_) { h[i] = 0.f; c[i] = 0.f; }
    if (i < B_*H_)   hbf[i] = __float2bfloat16(0.f);
    if (i < B_*E_)   ctxbf[i] = __float2bfloat16(0.f);
    if (i < T_*B_)   alpha[i] = (i < B_) ? 1.f : 0.f;
}

/* ---------------- conversions ---------------- */
__global__ void f2bf(const float* __restrict__ src, __nv_bfloat16* __restrict__ dst, size_t n) {
    size_t i = (size_t)blockIdx.x * blockDim.x + threadIdx.x;
    if (i < n) dst[i] = __float2bfloat16(src[i]);
}
__global__ void f2bf_strided(const float* __restrict__ src, int ld, int off,
                             __nv_bfloat16* __restrict__ dst, int cols, size_t n) {
    size_t i = (size_t)blockIdx.x * blockDim.x + threadIdx.x;
    if (i >= n) return;
    size_t r = i / cols, c = i % cols;
    dst[i] = __float2bfloat16(src[r * (size_t)ld + off + c]);
}

/* ---------------- embedding gather ---------------- */
__global__ void gather_emb(const float* __restrict__ emb_table,
                           const int* __restrict__ label,
                           float* __restrict__ emb) {
    int r = blockIdx.x;
    int n = label[r];
    const float* src = emb_table + (size_t)n * E_;
    float* dst = emb + (size_t)r * E_;
    for (int i = threadIdx.x; i < E_; i += blockDim.x) dst[i] = src[i];
}

/* ---------------- transpose (512,2048) -> (2048,512) ---------------- */
__global__ void transposeEH(const float* __restrict__ A, float* __restrict__ At) {
    __shared__ float tile[32][33];
    int x0 = blockIdx.x * 32, y0 = blockIdx.y * 32;
    int tx = threadIdx.x, ty = threadIdx.y;
    for (int j = 0; j < 32; j += 8)
        tile[ty+j][tx] = A[(size_t)(y0+ty+j) * H_ + x0 + tx];
    __syncthreads();
    for (int j = 0; j < 32; j += 8)
        At[(size_t)(x0+ty+j) * E_ + y0 + tx] = tile[tx][ty+j];
}

/* ============ tf32 tensor-core GEMM with register-prefetch pipeline ============ */
#define TKC 32
#define TKP (TKC+4)
__global__ __launch_bounds__(256) void tgemm_tn(
        const float* __restrict__ W, int ldw,
        const float* __restrict__ X, int ldx,
        const float* __restrict__ bias,
        float* __restrict__ C, size_t ldcw, size_t ldcx,
        int M, int Nx, int K)
{
    __shared__ unsigned Ws[128][TKP];
    __shared__ unsigned Xs[64][TKP];
    int tid = threadIdx.x;
    int wid = tid >> 5, lane = tid & 31;
    int wm = (wid & 3) * 32;
    int wn = (wid >> 2) * 32;
    int m0 = blockIdx.y * 128;
    int n0 = blockIdx.x * 64;
    int g = lane >> 2, t = lane & 3;

    int wrow = tid >> 1, wcol = (tid & 1) * 16;
    int xrow = tid >> 2, xcol = (tid & 3) * 8;

    float4 wreg[4], xreg[2];

#pragma unroll
    for (int i = 0; i < 4; i++) {
        wreg[i] = make_float4(0.f,0.f,0.f,0.f);
        if (m0 + wrow < M)
            wreg[i] = *(const float4*)(W + (size_t)(m0 + wrow) * ldw + wcol + i*4);
    }
#pragma unroll
    for (int i = 0; i < 2; i++) {
        xreg[i] = make_float4(0.f,0.f,0.f,0.f);
        if (n0 + xrow < Nx)
            xreg[i] = *(const float4*)(X + (size_t)(n0 + xrow) * ldx + xcol + i*4);
    }

    float c[2][4][4];
#pragma unroll
    for (int i = 0; i < 2; i++)
#pragma unroll
        for (int j = 0; j < 4; j++)
#pragma unroll
            for (int q = 0; q < 4; q++) c[i][j][q] = 0.f;

    for (int k0 = 0; k0 < K; k0 += TKC) {
#pragma unroll
        for (int i = 0; i < 4; i++) {
            Ws[wrow][wcol+i*4+0] = tf32c(wreg[i].x); Ws[wrow][wcol+i*4+1] = tf32c(wreg[i].y);
            Ws[wrow][wcol+i*4+2] = tf32c(wreg[i].z); Ws[wrow][wcol+i*4+3] = tf32c(wreg[i].w);
        }
#pragma unroll
        for (int i = 0; i < 2; i++) {
            Xs[xrow][xcol+i*4+0] = tf32c(xreg[i].x); Xs[xrow][xcol+i*4+1] = tf32c(xreg[i].y);
            Xs[xrow][xcol+i*4+2] = tf32c(xreg[i].z); Xs[xrow][xcol+i*4+3] = tf32c(xreg[i].w);
        }
        __syncthreads();

        int k1 = k0 + TKC;
        if (k1 < K) {
#pragma unroll
            for (int i = 0; i < 4; i++) {
                wreg[i] = make_float4(0.f,0.f,0.f,0.f);
                if (m0 + wrow < M)
                    wreg[i] = *(const float4*)(W + (size_t)(m0 + wrow) * ldw + k1 + wcol + i*4);
            }
#pragma unroll
            for (int i = 0; i < 2; i++) {
                xreg[i] = make_float4(0.f,0.f,0.f,0.f);
                if (n0 + xrow < Nx)
                    xreg[i] = *(const float4*)(X + (size_t)(n0 + xrow) * ldx + k1 + xcol + i*4);
            }
        }

#pragma unroll
        for (int kk = 0; kk < TKC; kk += 8) {
            unsigned a[2][4];
#pragma unroll
            for (int mt = 0; mt < 2; mt++) {
                int br = wm + mt*16;
                a[mt][0] = Ws[br + g    ][kk + t];
                a[mt][1] = Ws[br + g + 8][kk + t];
                a[mt][2] = Ws[br + g    ][kk + t + 4];
                a[mt][3] = Ws[br + g + 8][kk + t + 4];
            }
            unsigned b[4][2];
#pragma unroll
            for (int nt = 0; nt < 4; nt++) {
                b[nt][0] = Xs[wn + nt*8 + g][kk + t];
                b[nt][1] = Xs[wn + nt*8 + g][kk + t + 4];
            }
#pragma unroll
            for (int mt = 0; mt < 2; mt++)
#pragma unroll
                for (int nt = 0; nt < 4; nt++) {
                    asm volatile(
                        "mma.sync.aligned.m16n8k8.row.col.f32.tf32.tf32.f32 "
                        "{%0,%1,%2,%3}, {%4,%5,%6,%7}, {%8,%9}, {%0,%1,%2,%3};"
                        : "+f"(c[mt][nt][0]), "+f"(c[mt][nt][1]),
                          "+f"(c[mt][nt][2]), "+f"(c[mt][nt][3])
                        : "r"(a[mt][0]), "r"(a[mt][1]), "r"(a[mt][2]), "r"(a[mt][3]),
                          "r"(b[nt][0]), "r"(b[nt][1]));
                }
        }
        __syncthreads();
    }

#pragma unroll
    for (int mt = 0; mt < 2; mt++) {
#pragma unroll
        for (int nt = 0; nt < 4; nt++) {
            int row0 = m0 + wm + mt*16 + g;
            int col0 = n0 + wn + nt*8 + 2*t;
#pragma unroll
            for (int half = 0; half < 2; half++) {
                int row = row0 + half*8;
                if (row >= M) continue;
                float bv = bias ? bias[row] : 0.f;
                if (col0 < Nx)
                    C[(size_t)row*ldcw + (size_t)col0*ldcx] = c[mt][nt][half*2+0] + bv;
                if (col0 + 1 < Nx)
                    C[(size_t)row*ldcw + (size_t)(col0+1)*ldcx] = c[mt][nt][half*2+1] + bv;
            }
        }
    }
}

/* ================ PERSISTENT DECODER LOOP ================ */
__global__ __launch_bounds__(NT) void decoder_loop(
        const float* __restrict__ x, const float* __restrict__ mask,
        const __nv_bfloat16* __restrict__ whh, const __nv_bfloat16* __restrict__ wihc,
        const float* __restrict__ wproj, const float* __restrict__ comb,
        const float* __restrict__ eg,
        const float* __restrict__ v_m, const float* __restrict__ v_c,
        const float* __restrict__ r_m,
        const float* __restrict__ xh_m, const float* __restrict__ xh_c,
        const float* __restrict__ emb, const float* __restrict__ W_lm,
        float* __restrict__ out_lm,
        float* gates, float* hb, float* cb, float* alb,
        __nv_bfloat16* hbf, __nv_bfloat16* ctxbf,
        float* smv, float* scv, float* pv, float* uvv,
        float* scall)
{
    __shared__ float shA[T_], shB[T_], shC[T_], shD[T_], shR[T_], shBeta[T_];
    int tid = threadIdx.x;
    int lane = tid & 31;
    int gw = blockIdx.x * (NT/32) + (tid >> 5);
    int NW = gridDim.x * (NT/32);
    int gtid = blockIdx.x * NT + tid;
    int NTH = gridDim.x * NT;

    for (int u = 0; u < U_; u++) {
        float*       h_out = hb + ((u&1)^1)*(B_*H_);
        const float* c_in  = cb + (u&1)*(B_*H_);
        float*       c_out = cb + ((u&1)^1)*(B_*H_);
        const float* al_in  = alb + (u&1)*(T_*B_);
        float*       al_out = alb + ((u&1)^1)*(T_*B_);
        const float* eg_u = eg + (size_t)u*B_*G4H;
        float*       sc_u = scall + (size_t)u*B_*(2*E_);

        /* ---- Phase A: gates, 2 rows per warp (shared act loads) ---- */
        for (int jr = gw; jr < G4H/2; jr += NW) {
            int r0 = jr*2, r1 = r0 + 1;
            float acc0[16], acc1[16];
#pragma unroll
            for (int b = 0; b < 16; b++) { acc0[b] = 0.f; acc1[b] = 0.f; }
            {
                const __nv_bfloat16* w0 = wihc + (size_t)r0 * E_;
                const __nv_bfloat16* w1 = wihc + (size_t)r1 * E_;
                for (int k = lane*8; k < E_; k += 256) {
                    float wv0[8]; bf8(*(const float4*)(w0 + k), wv0);
                    float wv1[8]; bf8(*(const float4*)(w1 + k), wv1);
#pragma unroll
                    for (int b = 0; b < 16; b++) {
                        float av[8]; bf8(*(const float4*)(ctxbf + b*E_ + k), av);
                        acc0[b] += wv0[0]*av[0]+wv0[1]*av[1]+wv0[2]*av[2]+wv0[3]*av[3]
                                 + wv0[4]*av[4]+wv0[5]*av[5]+wv0[6]*av[6]+wv0[7]*av[7];
                        acc1[b] += wv1[0]*av[0]+wv1[1]*av[1]+wv1[2]*av[2]+wv1[3]*av[3]
                                 + wv1[4]*av[4]+wv1[5]*av[5]+wv1[6]*av[6]+wv1[7]*av[7];
                    }
                }
            }
            {
                const __nv_bfloat16* w0 = whh + (size_t)r0 * H_;
                const __nv_bfloat16* w1 = whh + (size_t)r1 * H_;
                for (int k = lane*8; k < H_; k += 256) {
                    float wv0[8]; bf8(*(const float4*)(w0 + k), wv0);
                    float wv1[8]; bf8(*(const float4*)(w1 + k), wv1);
#pragma unroll
                    for (int b = 0; b < 16; b++) {
                        float av[8]; bf8(*(const float4*)(hbf + b*H_ + k), av);
                        acc0[b] += wv0[0]*av[0]+wv0[1]*av[1]+wv0[2]*av[2]+wv0[3]*av[3]
                                 + wv0[4]*av[4]+wv0[5]*av[5]+wv0[6]*av[6]+wv0[7]*av[7];
                        acc1[b] += wv1[0]*av[0]+wv1[1]*av[1]+wv1[2]*av[2]+wv1[3]*av[3]
                                 + wv1[4]*av[4]+wv1[5]*av[5]+wv1[6]*av[6]+wv1[7]*av[7];
                    }
                }
            }
#pragma unroll
            for (int b = 0; b < 16; b++) {
#pragma unroll
                for (int off = 16; off > 0; off >>= 1) {
                    acc0[b] += __shfl_xor_sync(0xffffffffu, acc0[b], off);
                    acc1[b] += __shfl_xor_sync(0xffffffffu, acc1[b], off);
                }
            }
            if (lane < 16) {
                gates[(size_t)lane*G4H + r0] = acc0[lane] + eg_u[(size_t)lane*G4H + r0];
                gates[(size_t)lane*G4H + r1] = acc1[lane] + eg_u[(size_t)lane*G4H + r1];
            }
        }
        gbar();

        /* ---- Phase B: LSTM pointwise ---- */
        for (int i = gtid; i < B_*H_; i += NTH) {
            int b = i >> 11, k = i & (H_-1);
            const float* g = gates + (size_t)b * G4H;
            float gi = g[k], gf = g[H_ + k], gg = g[2*H_ + k], go = g[3*H_ + k];
            float cn = sigm(gf) * c_in[i] + sigm(gi) * tanhf(gg);
            c_out[i] = cn;
            float hn = sigm(go) * tanhf(cn);
            h_out[i] = hn;
            hbf[i] = __float2bfloat16(hn);
        }
        gbar();

        /* ---- Phase C: s / sm / sc ---- */
        for (int r = gw; r < 3*E_; r += NW) {
            const float* Wr = (r < E_) ? (wproj + (size_t)r * H_)
                                       : (comb + (size_t)(r - E_) * H_);
            float acc[16];
#pragma unroll
            for (int b = 0; b < 16; b++) acc[b] = 0.f;
            for (int k = lane*4; k < H_; k += 128) {
                float4 wv = *(const float4*)(Wr + k);
#pragma unroll
                for (int b = 0; b < 16; b++) {
                    float4 a = *(const float4*)(h_out + (size_t)b*H_ + k);
                    acc[b] += wv.x*a.x + wv.y*a.y + wv.z*a.z + wv.w*a.w;
                }
            }
#pragma unroll
            for (int b = 0; b < 16; b++)
#pragma unroll
                for (int off = 16; off > 0; off >>= 1)
                    acc[b] += __shfl_xor_sync(0xffffffffu, acc[b], off);
            if (lane < 16) {
                float v = acc[lane];
                if (r < E_)            sc_u[lane*(2*E_) + r] = v;
                else if (r < 2*E_)     smv[lane*E_ + (r - E_)] = v;
                else                   scv[lane*E_ + (r - 2*E_)] = v;
            }
        }
        gbar();

        /* ---- Phase D: energies ---- */
        for (int w = gw; w < T_*B_; w += NW) {
            int tt = w >> 4, b = w & 15;
            const float* xmp = xh_m + (size_t)(tt*B_ + b) * E_;
            const float* xcp = xh_c + (size_t)(tt*B_ + b) * E_;
            const float* smp = smv + (size_t)b * E_;
            const float* scp = scv + (size_t)b * E_;
            float am = 0.f, ac = 0.f;
            for (int e = lane*4; e < E_; e += 128) {
                float4 a  = *(const float4*)(xmp + e);
                float4 s4 = *(const float4*)(smp + e);
                float4 v4 = *(const float4*)(v_m + e);
                am += v4.x*tanha(a.x+s4.x) + v4.y*tanha(a.y+s4.y)
                    + v4.z*tanha(a.z+s4.z) + v4.w*tanha(a.w+s4.w);
                float4 a2  = *(const float4*)(xcp + e);
                float4 s42 = *(const float4*)(scp + e);
                float4 v42 = *(const float4*)(v_c + e);
                ac += v42.x*tanha(a2.x+s42.x) + v42.y*tanha(a2.y+s42.y)
                    + v42.z*tanha(a2.z+s42.z) + v42.w*tanha(a2.w+s42.w);
            }
#pragma unroll
            for (int off = 16; off > 0; off >>= 1) {
                am += __shfl_xor_sync(0xffffffffu, am, off);
                ac += __shfl_xor_sync(0xffffffffu, ac, off);
            }
            if (lane == 0) {
                float mk = mask[b*T_ + tt];
                pv[tt*B_ + b] = sigm(am + r_m[0]) * mk;
                uvv[tt*B_ + b] = ac;
            }
        }
        gbar();

        /* ---- Phase E+F: blocks 0..15 scan+ctx; blocks 16.. do lm chunk u ---- */
        if (blockIdx.x < B_) {
            int b = blockIdx.x, tt = tid;
            float pvv = pv[tt*B_ + b];
            float uvl = uvv[tt*B_ + b];
            float ap  = al_in[tt*B_ + b];
            float mk  = mask[b*T_ + tt];

            shR[tt] = uvl; __syncthreads();
            for (int off = 128; off > 0; off >>= 1) {
                if (tt < off) shR[tt] = fmaxf(shR[tt], shR[tt+off]);
                __syncthreads();
            }
            float um = shR[0];

            float eu = expf(uvl - um) * mk;
            shA[tt] = eu; __syncthreads();
#pragma unroll
            for (int off = 1; off < T_; off <<= 1) {
                float xv = (tt >= off) ? shA[tt-off] : 0.f;
                __syncthreads(); shA[tt] += xv; __syncthreads();
            }
            float denom = shA[tt] - (tt >= 8 ? shA[tt-8] : 0.f);

            shB[tt] = 1.f - pvv; __syncthreads();
#pragma unroll
            for (int off = 1; off < T_; off <<= 1) {
                float xv = (tt >= off) ? shB[tt-off] : 1.f;
                __syncthreads(); shB[tt] *= xv; __syncthreads();
            }
            float cp = (tt == 0) ? 1.f : shB[tt-1];

            shC[tt] = ap / fmaxf(cp, EPS_); __syncthreads();
#pragma unroll
            for (int off = 1; off < T_; off <<= 1) {
                float xv = (tt >= off) ? shC[tt-off] : 0.f;
                __syncthreads(); shC[tt] += xv; __syncthreads();
            }
            float av = pvv * cp * shC[tt];

            shD[tt] = av / fmaxf(denom, EPS_); __syncthreads();
#pragma unroll
            for (int off = 1; off < T_; off <<= 1) {
                float xv = (tt >= off) ? shD[tt-off] : 0.f;
                __syncthreads(); shD[tt] += xv; __syncthreads();
            }
            int hi = (tt + 7 > T_-1) ? (T_-1) : (tt + 7);
            float bv = eu * (shD[hi] - (tt > 0 ? shD[tt-1] : 0.f));

            al_out[tt*B_ + b] = av;
            shBeta[tt] = bv;
            __syncthreads();

            for (int d = tid; d < E_; d += NT) {
                const float* xp = x + (size_t)b*E_ + d;
                float acc = 0.f;
#pragma unroll 8
                for (int q = 0; q < T_; q++)
                    acc += shBeta[q] * xp[(size_t)q * B_ * E_];
                sc_u[(size_t)b*(2*E_) + E_ + d] = acc;
                ctxbf[(size_t)b * E_ + d] = __float2bfloat16(acc);
            }
        } else {
            /* lm chunk u: rows [u*LMROWS, min(N, (u+1)*LMROWS)), fp32 exact.
               1920 warps; warp keeps one 16-ub group across its rows. */
            int w2 = (blockIdx.x - B_) * (NT/32) + (tid >> 5);   /* 0..1919 */
            int grp = w2 % 48, rseq = w2 / 48;                    /* rseq 0..39 */
            int ub0 = grp * 16;
            int cs = u * LMROWS;
            int ce = cs + LMROWS; if (ce > N_) ce = N_;
#pragma unroll 1
            for (int j = 0; j < 8; j++) {
                int row = cs + rseq + 40*j;
                if (row >= ce) break;
                const float* wr = W_lm + (size_t)row * E_;
                float acc[16];
#pragma unroll
                for (int b = 0; b < 16; b++) acc[b] = 0.f;
                for (int k = lane*4; k < E_; k += 128) {
                    float4 wv = *(const float4*)(wr + k);
#pragma unroll
                    for (int b = 0; b < 16; b++) {
                        float4 a = *(const float4*)(emb + (size_t)(ub0 + b)*E_ + k);
                        acc[b] += wv.x*a.x + wv.y*a.y + wv.z*a.z + wv.w*a.w;
                    }
                }
#pragma unroll
                for (int b = 0; b < 16; b++)
#pragma unroll
                    for (int off = 16; off > 0; off >>= 1)
                        acc[b] += __shfl_xor_sync(0xffffffffu, acc[b], off);
                if (lane < 16)
                    out_lm[(size_t)row * (U_*B_) + ub0 + lane] = acc[lane];
            }
        }
        gbar();
    }
}

/* ---------------- host launcher ---------------- */
extern "C" void kernel_launch(void* const* d_in, const int* in_sizes, int n_in,
                              void* d_out, int out_size)
{
    const float* x        = (const float*)d_in[0];
    const float* att_mask = (const float*)d_in[1];
    const float* emb_tab  = (const float*)d_in[2];
    const float* W_ih     = (const float*)d_in[3];
    const float* W_hh     = (const float*)d_in[4];
    const float* b_lstm   = (const float*)d_in[5];
    const float* W_proj   = (const float*)d_in[6];
    const float* Ws_m     = (const float*)d_in[7];
    const float* Wh_m     = (const float*)d_in[8];
    const float* v_m      = (const float*)d_in[9];
    const float* r_m      = (const float*)d_in[10];
    const float* Ws_c     = (const float*)d_in[11];
    const float* Wh_c     = (const float*)d_in[12];
    const float* v_c      = (const float*)d_in[13];
    const float* W_am     = (const float*)d_in[14];
    const float* W_lm     = (const float*)d_in[15];
    const int*   label    = (const int*)d_in[16];

    float* out_am = (float*)d_out;
    float* out_lm = out_am + (size_t)N_ * U_ * B_;

    float *xh_m, *xh_c, *emb, *eg, *gates, *hb, *cb, *alb, *sm, *sc, *p, *uu, *scall, *wpT, *comb;
    __nv_bfloat16 *whh_bf, *wihc_bf, *hbf, *ctxbf;
    cudaGetSymbolAddress((void**)&xh_m,  g_xh_m);
    cudaGetSymbolAddress((void**)&xh_c,  g_xh_c);
    cudaGetSymbolAddress((void**)&emb,   g_emb);
    cudaGetSymbolAddress((void**)&eg,    g_eg);
    cudaGetSymbolAddress((void**)&gates, g_gates);
    cudaGetSymbolAddress((void**)&hb,    g_h);
    cudaGetSymbolAddress((void**)&cb,    g_c);
    cudaGetSymbolAddress((void**)&alb,   g_alpha);
    cudaGetSymbolAddress((void**)&sm,    g_sm);
    cudaGetSymbolAddress((void**)&sc,    g_sc);
    cudaGetSymbolAddress((void**)&p,     g_p);
    cudaGetSymbolAddress((void**)&uu,    g_u);
    cudaGetSymbolAddress((void**)&scall, g_scall);
    cudaGetSymbolAddress((void**)&wpT,   g_wpT);
    cudaGetSymbolAddress((void**)&comb,  g_comb);
    cudaGetSymbolAddress((void**)&whh_bf,  g_whh_bf);
    cudaGetSymbolAddress((void**)&wihc_bf, g_wihc_bf);
    cudaGetSymbolAddress((void**)&hbf,   g_hbf);
    cudaGetSymbolAddress((void**)&ctxbf, g_ctxbf);

    init_state<<<(2*B_*H_ + 255)/256, 256>>>(hb, cb, alb, hbf, ctxbf);

    {
        size_t n;
        n = (size_t)G4H*H_; f2bf<<<(int)((n+511)/512), 512>>>(W_hh, whh_bf, n);
        n = (size_t)G4H*E_; f2bf_strided<<<(int)((n+511)/512), 512>>>(W_ih, 2*E_, E_, wihc_bf, E_, n);
    }

    gather_emb<<<U_*B_, 128>>>(emb_tab, label, emb);

    /* encoder-side projections */
    tgemm_tn<<<dim3((T_*B_+63)/64, (E_+127)/128), 256>>>(Wh_m, E_, x, E_, nullptr,
            xh_m, 1, E_, E_, T_*B_, E_);
    tgemm_tn<<<dim3((T_*B_+63)/64, (E_+127)/128), 256>>>(Wh_c, E_, x, E_, nullptr,
            xh_c, 1, E_, E_, T_*B_, E_);

    /* eg = emb @ W_ih[:, :E]^T + b_lstm */
    tgemm_tn<<<dim3((U_*B_+63)/64, (G4H+127)/128), 256>>>(W_ih, 2*E_, emb, E_, b_lstm,
            eg, 1, G4H, G4H, U_*B_, E_);

    /* folds: comb = [Ws_m@W_proj ; Ws_c@W_proj] */
    transposeEH<<<dim3(H_/32, E_/32), dim3(32, 8)>>>(W_proj, wpT);
    tgemm_tn<<<dim3((H_+63)/64, (E_+127)/128), 256>>>(Ws_m, E_, wpT, E_, nullptr,
            comb, H_, 1, E_, H_, E_);
    tgemm_tn<<<dim3((H_+63)/64, (E_+127)/128), 256>>>(Ws_c, E_, wpT, E_, nullptr,
            comb + (size_t)E_*H_, H_, 1, E_, H_, E_);

    /* 48-step recurrence in one persistent kernel (lm output computed inside) */
    decoder_loop<<<GRID, NT>>>(x, att_mask, whh_bf, wihc_bf, W_proj, comb,
            eg, v_m, v_c, r_m, xh_m, xh_c,
            emb, W_lm, out_lm,
            gates, hb, cb, alb, hbf, ctxbf,
            sm, sc, p, uu, scall);

    /* am output */
    tgemm_tn<<<dim3((U_*B_+63)/64, (N_+127)/128), 256>>>(W_am, 2*E_, scall, 2*E_, nullptr,
            out_am, U_*B_, 1, N_, U_*B_, 2*E_);
}

// round 12
// speedup vs baseline: 1.5446x; 1.5446x over previous
#include <cuda_runtime.h>
#include <cuda_bf16.h>
#include <math.h>

#define T_ 256
#define B_ 16
#define E_ 512
#define H_ 2048
#define N_ 14839
#define U_ 48
#define G4H 8192
#define KA 2560               /* combined act length: 512 ctx + 2048 h */
#define KHF 1280              /* k-split half */
#define EPS_ 1e-6f
#define NT 256
#define GRID 256
#define APAD 2568             /* act smem row stride (bf16): 2560 + 8 -> bank-safe */
#define WPAD 72               /* weight smem row stride per 64-chunk: 64 + 8 */
#define SMEM_DYN ((16*APAD + 2*32*WPAD) * 2)   /* 91392 bytes */

/* ---------------- scratch ---------------- */
__device__ float g_xh_m[T_*B_*E_];
__device__ float g_xh_c[T_*B_*E_];
__device__ float g_emb[U_*B_*E_];
__device__ float g_eg[(size_t)U_*B_*G4H];
__device__ float g_gates[(size_t)B_*G4H];
__device__ float g_h[2][B_*H_];
__device__ float g_c[2][B_*H_];
__device__ float g_alpha[2][T_*B_];
__device__ float g_sm[B_*E_];
__device__ float g_sc[B_*E_];
__device__ float g_p[T_*B_];
__device__ float g_u[T_*B_];
__device__ float g_beta[T_*B_];
__device__ float g_scall[U_*B_*2*E_];
__device__ float g_wpT[H_*E_];
__device__ float g_comb[2*E_*H_];
__device__ __nv_bfloat16 g_wcomb[(size_t)G4H*KA];  /* [Wih_ctx | Whh] bf16, row-major K=2560 */
__device__ __nv_bfloat16 g_actbf[B_*KA];           /* [ctx | h] bf16 */

/* grid barrier state */
__device__ unsigned g_cnt = 0;
__device__ volatile unsigned g_gen = 0;

__device__ __forceinline__ void gbar() {
    __syncthreads();
    if (threadIdx.x == 0) {
        unsigned gen = g_gen;
        __threadfence();
        if (atomicAdd(&g_cnt, 1u) == gridDim.x - 1u) {
            g_cnt = 0;
            __threadfence();
            g_gen = gen + 1u;
        } else {
            while (g_gen == gen) __nanosleep(32);
        }
        __threadfence();
    }
    __syncthreads();
}

__device__ __forceinline__ float sigm(float x) { return 1.f / (1.f + expf(-x)); }
__device__ __forceinline__ float tanha(float x) {
    float y; asm("tanh.approx.f32 %0, %1;" : "=f"(y) : "f"(x)); return y;
}
__device__ __forceinline__ unsigned tf32c(float x) {
    unsigned r; asm("cvt.rna.tf32.f32 %0, %1;" : "=r"(r) : "f"(x)); return r;
}

/* ---------------- init ---------------- */
__global__ void init_state(float* h, float* c, float* alpha, __nv_bfloat16* actbf) {
    int i = blockIdx.x * blockDim.x + threadIdx.x;
    if (i < 2*B_*H_) { h[i] = 0.f; c[i] = 0.f; }
    if (i < B_*KA)   actbf[i] = __float2bfloat16(0.f);
    if (i < T_*B_)   alpha[i] = (i < B_) ? 1.f : 0.f;
}

/* ---------------- combined bf16 weight build ---------------- */
__global__ void build_wcomb(const float* __restrict__ W_ih, const float* __restrict__ W_hh,
                            __nv_bfloat16* __restrict__ wc) {
    size_t i = (size_t)blockIdx.x * blockDim.x + threadIdx.x;
    if (i >= (size_t)G4H * KA) return;
    int r = (int)(i / KA), k = (int)(i % KA);
    float v = (k < E_) ? W_ih[(size_t)r * (2*E_) + E_ + k]
                       : W_hh[(size_t)r * H_ + (k - E_)];
    wc[i] = __float2bfloat16(v);
}

/* ---------------- embedding gather ---------------- */
__global__ void gather_emb(const float* __restrict__ emb_table,
                           const int* __restrict__ label,
                           float* __restrict__ emb) {
    int r = blockIdx.x;
    int n = label[r];
    const float* src = emb_table + (size_t)n * E_;
    float* dst = emb + (size_t)r * E_;
    for (int i = threadIdx.x; i < E_; i += blockDim.x) dst[i] = src[i];
}

/* ---------------- transpose (512,2048) -> (2048,512) ---------------- */
__global__ void transposeEH(const float* __restrict__ A, float* __restrict__ At) {
    __shared__ float tile[32][33];
    int x0 = blockIdx.x * 32, y0 = blockIdx.y * 32;
    int tx = threadIdx.x, ty = threadIdx.y;
    for (int j = 0; j < 32; j += 8)
        tile[ty+j][tx] = A[(size_t)(y0+ty+j) * H_ + x0 + tx];
    __syncthreads();
    for (int j = 0; j < 32; j += 8)
        At[(size_t)(x0+ty+j) * E_ + y0 + tx] = tile[tx][ty+j];
}

/* ============ tf32 tensor-core GEMM (verified R7 form) ============ */
#define TKC 32
#define TKP (TKC+4)
__global__ __launch_bounds__(256) void tgemm_tn(
        const float* __restrict__ W, int ldw,
        const float* __restrict__ X, int ldx,
        const float* __restrict__ bias,
        float* __restrict__ C, size_t ldcw, size_t ldcx,
        int M, int Nx, int K)
{
    __shared__ unsigned Ws[128][TKP];
    __shared__ unsigned Xs[64][TKP];
    int tid = threadIdx.x;
    int wid = tid >> 5, lane = tid & 31;
    int wm = (wid & 3) * 32;
    int wn = (wid >> 2) * 32;
    int m0 = blockIdx.y * 128;
    int n0 = blockIdx.x * 64;
    int g = lane >> 2, t = lane & 3;

    float c[2][4][4];
#pragma unroll
    for (int i = 0; i < 2; i++)
#pragma unroll
        for (int j = 0; j < 4; j++)
#pragma unroll
            for (int q = 0; q < 4; q++) c[i][j][q] = 0.f;

    for (int k0 = 0; k0 < K; k0 += TKC) {
        {
            int r = tid >> 1;
            int cc = (tid & 1) * 16;
#pragma unroll
            for (int i = 0; i < 4; i++) {
                float4 v = make_float4(0.f,0.f,0.f,0.f);
                if (m0 + r < M)
                    v = *(const float4*)(W + (size_t)(m0 + r) * ldw + k0 + cc + i*4);
                Ws[r][cc+i*4+0] = tf32c(v.x); Ws[r][cc+i*4+1] = tf32c(v.y);
                Ws[r][cc+i*4+2] = tf32c(v.z); Ws[r][cc+i*4+3] = tf32c(v.w);
            }
        }
        {
            int r = tid >> 2;
            int cc = (tid & 3) * 8;
#pragma unroll
            for (int i = 0; i < 2; i++) {
                float4 v = make_float4(0.f,0.f,0.f,0.f);
                if (n0 + r < Nx)
                    v = *(const float4*)(X + (size_t)(n0 + r) * ldx + k0 + cc + i*4);
                Xs[r][cc+i*4+0] = tf32c(v.x); Xs[r][cc+i*4+1] = tf32c(v.y);
                Xs[r][cc+i*4+2] = tf32c(v.z); Xs[r][cc+i*4+3] = tf32c(v.w);
            }
        }
        __syncthreads();

#pragma unroll
        for (int kk = 0; kk < TKC; kk += 8) {
            unsigned a[2][4];
#pragma unroll
            for (int mt = 0; mt < 2; mt++) {
                int br = wm + mt*16;
                a[mt][0] = Ws[br + g    ][kk + t];
                a[mt][1] = Ws[br + g + 8][kk + t];
                a[mt][2] = Ws[br + g    ][kk + t + 4];
                a[mt][3] = Ws[br + g + 8][kk + t + 4];
            }
            unsigned b[4][2];
#pragma unroll
            for (int nt = 0; nt < 4; nt++) {
                b[nt][0] = Xs[wn + nt*8 + g][kk + t];
                b[nt][1] = Xs[wn + nt*8 + g][kk + t + 4];
            }
#pragma unroll
            for (int mt = 0; mt < 2; mt++)
#pragma unroll
                for (int nt = 0; nt < 4; nt++) {
                    asm volatile(
                        "mma.sync.aligned.m16n8k8.row.col.f32.tf32.tf32.f32 "
                        "{%0,%1,%2,%3}, {%4,%5,%6,%7}, {%8,%9}, {%0,%1,%2,%3};"
                        : "+f"(c[mt][nt][0]), "+f"(c[mt][nt][1]),
                          "+f"(c[mt][nt][2]), "+f"(c[mt][nt][3])
                        : "r"(a[mt][0]), "r"(a[mt][1]), "r"(a[mt][2]), "r"(a[mt][3]),
                          "r"(b[nt][0]), "r"(b[nt][1]));
                }
        }
        __syncthreads();
    }

#pragma unroll
    for (int mt = 0; mt < 2; mt++) {
#pragma unroll
        for (int nt = 0; nt < 4; nt++) {
            int row0 = m0 + wm + mt*16 + g;
            int col0 = n0 + wn + nt*8 + 2*t;
#pragma unroll
            for (int half = 0; half < 2; half++) {
                int row = row0 + half*8;
                if (row >= M) continue;
                float bv = bias ? bias[row] : 0.f;
                if (col0 < Nx)
                    C[(size_t)row*ldcw + (size_t)col0*ldcx] = c[mt][nt][half*2+0] + bv;
                if (col0 + 1 < Nx)
                    C[(size_t)row*ldcw + (size_t)(col0+1)*ldcx] = c[mt][nt][half*2+1] + bv;
            }
        }
    }
}

/* ================ PERSISTENT DECODER LOOP ================ */
__global__ __launch_bounds__(NT) void decoder_loop(
        const float* __restrict__ x, const float* __restrict__ mask,
        const __nv_bfloat16* __restrict__ wcomb,
        const float* __restrict__ wproj, const float* __restrict__ comb,
        const float* __restrict__ eg,
        const float* __restrict__ v_m, const float* __restrict__ v_c,
        const float* __restrict__ r_m,
        const float* __restrict__ xh_m, const float* __restrict__ xh_c,
        float* gates, float* hb, float* cb, float* alb,
        __nv_bfloat16* actbf,
        float* smv, float* scv, float* pv, float* uvv, float* betav,
        float* scall)
{
    extern __shared__ char dyn[];
    __nv_bfloat16* sACT = (__nv_bfloat16*)dyn;                 /* [16][APAD] */
    __nv_bfloat16* sWT  = sACT + 16*APAD;                      /* [2][32][WPAD] */
    float*         sPART = (float*)sWT;                        /* alias after sync: [4][16][8] */

    __shared__ float shA[T_], shB[T_], shC[T_], shD[T_], shR[T_];
    int tid = threadIdx.x;
    int lane = tid & 31;
    int wid = tid >> 5;
    int gw = blockIdx.x * (NT/32) + wid;
    int NW = gridDim.x * (NT/32);
    int gtid = blockIdx.x * NT + tid;
    int NTH = gridDim.x * NT;
    int g = lane >> 2, t = lane & 3;

    int n0 = blockIdx.x * 32;          /* this block's 32 gate rows */
    int nt = wid & 3;                   /* n8 tile within the 32 */
    int khalf = wid >> 2;               /* k-split half */

    for (int u = 0; u < U_; u++) {
        float*       h_out = hb + ((u&1)^1)*(B_*H_);
        const float* c_in  = cb + (u&1)*(B_*H_);
        float*       c_out = cb + ((u&1)^1)*(B_*H_);
        const float* al_in  = alb + (u&1)*(T_*B_);
        float*       al_out = alb + ((u&1)^1)*(T_*B_);
        const float* eg_u = eg + (size_t)u*B_*G4H;
        float*       sc_u = scall + (size_t)u*B_*(2*E_);

        /* ---- Phase A: gates via smem-staged bf16 MMA ----
           Block computes gates[:, n0:n0+32]; acts staged in smem, weights tiled. */
        /* stage acts: actbf[16][KA] -> sACT[16][APAD] (float4 = 8 bf16) */
        for (int idx = tid; idx < 16*(KA/8); idx += NT) {
            int b = idx / (KA/8), f = idx % (KA/8);
            *(float4*)(sACT + (size_t)b*APAD + f*8) =
                *(const float4*)(actbf + (size_t)b*KA + f*8);
        }
        __syncthreads();

        float c0 = 0.f, c1 = 0.f, c2 = 0.f, c3 = 0.f;
        for (int it = 0; it < KHF/64; it++) {
            int kc = it * 64;
            /* stage weight tiles for BOTH k-halves: 2 x 32 rows x 64 bf16 */
            for (int idx = tid; idx < 512; idx += NT) {
                int half = idx >> 8, row = (idx >> 3) & 31, f = idx & 7;
                *(float4*)(sWT + ((size_t)half*32 + row)*WPAD + f*8) =
                    *(const float4*)(wcomb + (size_t)(n0 + row)*KA + half*KHF + kc + f*8);
            }
            __syncthreads();

            const __nv_bfloat16* wrow = sWT + ((size_t)khalf*32 + nt*8 + g)*WPAD;
            const __nv_bfloat16* ar0 = sACT + (size_t)g*APAD + khalf*KHF + kc;
            const __nv_bfloat16* ar1 = sACT + (size_t)(g+8)*APAD + khalf*KHF + kc;
#pragma unroll
            for (int sub = 0; sub < 4; sub++) {
                int ks = sub*16;
                unsigned a0 = *(const unsigned*)(ar0 + ks + 2*t);
                unsigned a1 = *(const unsigned*)(ar1 + ks + 2*t);
                unsigned a2 = *(const unsigned*)(ar0 + ks + 2*t + 8);
                unsigned a3 = *(const unsigned*)(ar1 + ks + 2*t + 8);
                unsigned b0 = *(const unsigned*)(wrow + ks + 2*t);
                unsigned b1 = *(const unsigned*)(wrow + ks + 2*t + 8);
                asm volatile(
                    "mma.sync.aligned.m16n8k16.row.col.f32.bf16.bf16.f32 "
                    "{%0,%1,%2,%3}, {%4,%5,%6,%7}, {%8,%9}, {%0,%1,%2,%3};"
                    : "+f"(c0), "+f"(c1), "+f"(c2), "+f"(c3)
                    : "r"(a0), "r"(a1), "r"(a2), "r"(a3), "r"(b0), "r"(b1));
            }
            __syncthreads();
        }

        /* combine k-halves: khalf1 stores partials, khalf0 adds + eg -> gates */
        if (khalf == 1) {
            float* pp = sPART + (size_t)nt*128;
            pp[g*8 + 2*t]            = c0;
            pp[g*8 + 2*t + 1]        = c1;
            pp[(g+8)*8 + 2*t]        = c2;
            pp[(g+8)*8 + 2*t + 1]    = c3;
        }
        __syncthreads();
        if (khalf == 0) {
            const float* pp = sPART + (size_t)nt*128;
            int col0 = n0 + nt*8 + 2*t;
            gates[(size_t)g*G4H + col0]         = c0 + pp[g*8 + 2*t]         + eg_u[(size_t)g*G4H + col0];
            gates[(size_t)g*G4H + col0 + 1]     = c1 + pp[g*8 + 2*t + 1]     + eg_u[(size_t)g*G4H + col0 + 1];
            gates[(size_t)(g+8)*G4H + col0]     = c2 + pp[(g+8)*8 + 2*t]     + eg_u[(size_t)(g+8)*G4H + col0];
            gates[(size_t)(g+8)*G4H + col0 + 1] = c3 + pp[(g+8)*8 + 2*t + 1] + eg_u[(size_t)(g+8)*G4H + col0 + 1];
        }
        gbar();

        /* ---- Phase B: LSTM pointwise; write h (fp32) + bf16 into actbf ---- */
        for (int i = gtid; i < B_*H_; i += NTH) {
            int b = i >> 11, k = i & (H_-1);
            const float* gp = gates + (size_t)b * G4H;
            float gi = gp[k], gf = gp[H_ + k], gg = gp[2*H_ + k], go = gp[3*H_ + k];
            float cn = sigm(gf) * c_in[i] + sigm(gi) * tanhf(gg);
            c_out[i] = cn;
            float hn = sigm(go) * tanhf(cn);
            h_out[i] = hn;
            actbf[(size_t)b * KA + E_ + k] = __float2bfloat16(hn);
        }
        gbar();

        /* ---- Phase C: s / sm / sc (fp32) ---- */
        for (int r = gw; r < 3*E_; r += NW) {
            const float* Wr = (r < E_) ? (wproj + (size_t)r * H_)
                                       : (comb + (size_t)(r - E_) * H_);
            float acc[16];
#pragma unroll
            for (int b = 0; b < 16; b++) acc[b] = 0.f;
            for (int k = lane*4; k < H_; k += 128) {
                float4 wv = *(const float4*)(Wr + k);
#pragma unroll
                for (int b = 0; b < 16; b++) {
                    float4 a = *(const float4*)(h_out + (size_t)b*H_ + k);
                    acc[b] += wv.x*a.x + wv.y*a.y + wv.z*a.z + wv.w*a.w;
                }
            }
#pragma unroll
            for (int b = 0; b < 16; b++)
#pragma unroll
                for (int off = 16; off > 0; off >>= 1)
                    acc[b] += __shfl_xor_sync(0xffffffffu, acc[b], off);
            if (lane < 16) {
                float v = acc[lane];
                if (r < E_)            sc_u[lane*(2*E_) + r] = v;
                else if (r < 2*E_)     smv[lane*E_ + (r - E_)] = v;
                else                   scv[lane*E_ + (r - 2*E_)] = v;
            }
        }
        gbar();

        /* ---- Phase D: energies ---- */
        for (int w = gw; w < T_*B_; w += NW) {
            int tt = w >> 4, b = w & 15;
            const float* xmp = xh_m + (size_t)(tt*B_ + b) * E_;
            const float* xcp = xh_c + (size_t)(tt*B_ + b) * E_;
            const float* smp = smv + (size_t)b * E_;
            const float* scp = scv + (size_t)b * E_;
            float am = 0.f, ac = 0.f;
            for (int e = lane*4; e < E_; e += 128) {
                float4 a  = *(const float4*)(xmp + e);
                float4 s4 = *(const float4*)(smp + e);
                float4 v4 = *(const float4*)(v_m + e);
                am += v4.x*tanha(a.x+s4.x) + v4.y*tanha(a.y+s4.y)
                    + v4.z*tanha(a.z+s4.z) + v4.w*tanha(a.w+s4.w);
                float4 a2  = *(const float4*)(xcp + e);
                float4 s42 = *(const float4*)(scp + e);
                float4 v42 = *(const float4*)(v_c + e);
                ac += v42.x*tanha(a2.x+s42.x) + v42.y*tanha(a2.y+s42.y)
                    + v42.z*tanha(a2.z+s42.z) + v42.w*tanha(a2.w+s42.w);
            }
#pragma unroll
            for (int off = 16; off > 0; off >>= 1) {
                am += __shfl_xor_sync(0xffffffffu, am, off);
                ac += __shfl_xor_sync(0xffffffffu, ac, off);
            }
            if (lane == 0) {
                float mk = mask[b*T_ + tt];
                pv[tt*B_ + b] = sigm(am + r_m[0]) * mk;
                uvv[tt*B_ + b] = ac;
            }
        }
        gbar();

        /* ---- Phase E: per-b scans ---- */
        if (blockIdx.x < B_) {
            int b = blockIdx.x, tt = tid;
            float pvv = pv[tt*B_ + b];
            float uvl = uvv[tt*B_ + b];
            float ap  = al_in[tt*B_ + b];
            float mk  = mask[b*T_ + tt];

            shR[tt] = uvl; __syncthreads();
            for (int off = 128; off > 0; off >>= 1) {
                if (tt < off) shR[tt] = fmaxf(shR[tt], shR[tt+off]);
                __syncthreads();
            }
            float um = shR[0];

            float eu = expf(uvl - um) * mk;
            shA[tt] = eu; __syncthreads();
#pragma unroll
            for (int off = 1; off < T_; off <<= 1) {
                float xv = (tt >= off) ? shA[tt-off] : 0.f;
                __syncthreads(); shA[tt] += xv; __syncthreads();
            }
            float denom = shA[tt] - (tt >= 8 ? shA[tt-8] : 0.f);

            shB[tt] = 1.f - pvv; __syncthreads();
#pragma unroll
            for (int off = 1; off < T_; off <<= 1) {
                float xv = (tt >= off) ? shB[tt-off] : 1.f;
                __syncthreads(); shB[tt] *= xv; __syncthreads();
            }
            float cp = (tt == 0) ? 1.f : shB[tt-1];

            shC[tt] = ap / fmaxf(cp, EPS_); __syncthreads();
#pragma unroll
            for (int off = 1; off < T_; off <<= 1) {
                float xv = (tt >= off) ? shC[tt-off] : 0.f;
                __syncthreads(); shC[tt] += xv; __syncthreads();
            }
            float av = pvv * cp * shC[tt];

            shD[tt] = av / fmaxf(denom, EPS_); __syncthreads();
#pragma unroll
            for (int off = 1; off < T_; off <<= 1) {
                float xv = (tt >= off) ? shD[tt-off] : 0.f;
                __syncthreads(); shD[tt] += xv; __syncthreads();
            }
            int hi = (tt + 7 > T_-1) ? (T_-1) : (tt + 7);
            float bv = eu * (shD[hi] - (tt > 0 ? shD[tt-1] : 0.f));

            al_out[tt*B_ + b] = av;
            betav[tt*B_ + b] = bv;
        }
        gbar();

        /* ---- Phase F: ctx -> scall + actbf ---- */
        for (int i = gtid; i < B_*E_; i += NTH) {
            int b = i >> 9, d = i & (E_-1);
            const float* xp = x + (size_t)b*E_ + d;
            float acc = 0.f;
#pragma unroll 8
            for (int tq = 0; tq < T_; tq++)
                acc += betav[tq*B_ + b] * xp[(size_t)tq * B_ * E_];
            sc_u[(size_t)b*(2*E_) + E_ + d] = acc;
            actbf[(size_t)b * KA + d] = __float2bfloat16(acc);
        }
        gbar();
    }
}

/* ---------------- host launcher ---------------- */
extern "C" void kernel_launch(void* const* d_in, const int* in_sizes, int n_in,
                              void* d_out, int out_size)
{
    const float* x        = (const float*)d_in[0];
    const float* att_mask = (const float*)d_in[1];
    const float* emb_tab  = (const float*)d_in[2];
    const float* W_ih     = (const float*)d_in[3];
    const float* W_hh     = (const float*)d_in[4];
    const float* b_lstm   = (const float*)d_in[5];
    const float* W_proj   = (const float*)d_in[6];
    const float* Ws_m     = (const float*)d_in[7];
    const float* Wh_m     = (const float*)d_in[8];
    const float* v_m      = (const float*)d_in[9];
    const float* r_m      = (const float*)d_in[10];
    const float* Ws_c     = (const float*)d_in[11];
    const float* Wh_c     = (const float*)d_in[12];
    const float* v_c      = (const float*)d_in[13];
    const float* W_am     = (const float*)d_in[14];
    const float* W_lm     = (const float*)d_in[15];
    const int*   label    = (const int*)d_in[16];

    float* out_am = (float*)d_out;
    float* out_lm = out_am + (size_t)N_ * U_ * B_;

    float *xh_m, *xh_c, *emb, *eg, *gates, *hb, *cb, *alb, *sm, *sc, *p, *uu, *beta, *scall, *wpT, *comb;
    __nv_bfloat16 *wcomb, *actbf;
    cudaGetSymbolAddress((void**)&xh_m,  g_xh_m);
    cudaGetSymbolAddress((void**)&xh_c,  g_xh_c);
    cudaGetSymbolAddress((void**)&emb,   g_emb);
    cudaGetSymbolAddress((void**)&eg,    g_eg);
    cudaGetSymbolAddress((void**)&gates, g_gates);
    cudaGetSymbolAddress((void**)&hb,    g_h);
    cudaGetSymbolAddress((void**)&cb,    g_c);
    cudaGetSymbolAddress((void**)&alb,   g_alpha);
    cudaGetSymbolAddress((void**)&sm,    g_sm);
    cudaGetSymbolAddress((void**)&sc,    g_sc);
    cudaGetSymbolAddress((void**)&p,     g_p);
    cudaGetSymbolAddress((void**)&uu,    g_u);
    cudaGetSymbolAddress((void**)&beta,  g_beta);
    cudaGetSymbolAddress((void**)&scall, g_scall);
    cudaGetSymbolAddress((void**)&wpT,   g_wpT);
    cudaGetSymbolAddress((void**)&comb,  g_comb);
    cudaGetSymbolAddress((void**)&wcomb, g_wcomb);
    cudaGetSymbolAddress((void**)&actbf, g_actbf);

    init_state<<<(2*B_*H_ + 255)/256, 256>>>(hb, cb, alb, actbf);

    {
        size_t n = (size_t)G4H * KA;
        build_wcomb<<<(int)((n + 511)/512), 512>>>(W_ih, W_hh, wcomb);
    }

    gather_emb<<<U_*B_, 128>>>(emb_tab, label, emb);

    /* encoder-side projections */
    tgemm_tn<<<dim3((T_*B_+63)/64, (E_+127)/128), 256>>>(Wh_m, E_, x, E_, nullptr,
            xh_m, 1, E_, E_, T_*B_, E_);
    tgemm_tn<<<dim3((T_*B_+63)/64, (E_+127)/128), 256>>>(Wh_c, E_, x, E_, nullptr,
            xh_c, 1, E_, E_, T_*B_, E_);

    /* eg = emb @ W_ih[:, :E]^T + b_lstm */
    tgemm_tn<<<dim3((U_*B_+63)/64, (G4H+127)/128), 256>>>(W_ih, 2*E_, emb, E_, b_lstm,
            eg, 1, G4H, G4H, U_*B_, E_);

    /* lm output */
    tgemm_tn<<<dim3((U_*B_+63)/64, (N_+127)/128), 256>>>(W_lm, E_, emb, E_, nullptr,
            out_lm, U_*B_, 1, N_, U_*B_, E_);

    /* folds: comb = [Ws_m@W_proj ; Ws_c@W_proj] */
    transposeEH<<<dim3(H_/32, E_/32), dim3(32, 8)>>>(W_proj, wpT);
    tgemm_tn<<<dim3((H_+63)/64, (E_+127)/128), 256>>>(Ws_m, E_, wpT, E_, nullptr,
            comb, H_, 1, E_, H_, E_);
    tgemm_tn<<<dim3((H_+63)/64, (E_+127)/128), 256>>>(Ws_c, E_, wpT, E_, nullptr,
            comb + (size_t)E_*H_, H_, 1, E_, H_, E_);

    /* 48-step recurrence in one persistent kernel */
    static int smem_set = 0;
    if (!smem_set) {
        cudaFuncSetAttribute(decoder_loop, cudaFuncAttributeMaxDynamicSharedMemorySize, SMEM_DYN);
        smem_set = 1;
    }
    decoder_loop<<<GRID, NT, SMEM_DYN>>>(x, att_mask, wcomb, W_proj, comb,
            eg, v_m, v_c, r_m, xh_m, xh_c,
            gates, hb, cb, alb, actbf,
            sm, sc, p, uu, beta, scall);

    /* am output */
    tgemm_tn<<<dim3((U_*B_+63)/64, (N_+127)/128), 256>>>(W_am, 2*E_, scall, 2*E_, nullptr,
            out_am, U_*B_, 1, N_, U_*B_, 2*E_);
}

// round 13
// speedup vs baseline: 1.5478x; 1.0020x over previous
#include <cuda_runtime.h>
#include <cuda_bf16.h>
#include <math.h>

#define T_ 256
#define B_ 16
#define E_ 512
#define H_ 2048
#define N_ 14839
#define U_ 48
#define G4H 8192
#define KA 2560               /* combined act length: 512 ctx + 2048 h */
#define KHF 1280              /* k-split half */
#define EPS_ 1e-6f
#define NT 256
#define GRID 256
#define APAD 2568             /* act smem row stride (bf16) */
#define WPAD 72               /* weight smem row stride per 64-chunk */
#define SMEM_DYN ((16*APAD + 2*32*WPAD) * 2)   /* 91392 bytes */

/* ---------------- scratch ---------------- */
__device__ float g_xh_m[T_*B_*E_];
__device__ float g_xh_c[T_*B_*E_];
__device__ float g_emb[U_*B_*E_];
__device__ float g_eg[(size_t)U_*B_*G4H];
__device__ float g_gates[(size_t)B_*G4H];
__device__ float g_h[2][B_*H_];
__device__ float g_c[2][B_*H_];
__device__ float g_alpha[2][T_*B_];
__device__ float g_sm[B_*E_];
__device__ float g_sc[B_*E_];
__device__ float g_p[T_*B_];
__device__ float g_u[T_*B_];
__device__ float g_beta[T_*B_];
__device__ float g_scall[U_*B_*2*E_];
__device__ float g_wpT[H_*E_];
__device__ float g_comb[2*E_*H_];
__device__ __nv_bfloat16 g_wcomb[(size_t)G4H*KA];
__device__ __nv_bfloat16 g_actbf[B_*KA];

/* grid barrier state */
__device__ unsigned g_cnt = 0;
__device__ volatile unsigned g_gen = 0;

__device__ __forceinline__ void gbar() {
    __syncthreads();
    if (threadIdx.x == 0) {
        unsigned gen = g_gen;
        __threadfence();
        if (atomicAdd(&g_cnt, 1u) == gridDim.x - 1u) {
            g_cnt = 0;
            __threadfence();
            g_gen = gen + 1u;
        } else {
            while (g_gen == gen) __nanosleep(32);
        }
        __threadfence();
    }
    __syncthreads();
}

__device__ __forceinline__ float sigm(float x) { return 1.f / (1.f + expf(-x)); }
__device__ __forceinline__ float tanha(float x) {
    float y; asm("tanh.approx.f32 %0, %1;" : "=f"(y) : "f"(x)); return y;
}
__device__ __forceinline__ unsigned tf32c(float x) {
    unsigned r; asm("cvt.rna.tf32.f32 %0, %1;" : "=r"(r) : "f"(x)); return r;
}

/* ---------------- init ---------------- */
__global__ void init_state(float* h, float* c, float* alpha, __nv_bfloat16* actbf) {
    int i = blockIdx.x * blockDim.x + threadIdx.x;
    if (i < 2*B_*H_) { h[i] = 0.f; c[i] = 0.f; }
    if (i < B_*KA)   actbf[i] = __float2bfloat16(0.f);
    if (i < T_*B_)   alpha[i] = (i < B_) ? 1.f : 0.f;
}

/* ---------------- combined bf16 weight build ---------------- */
__global__ void build_wcomb(const float* __restrict__ W_ih, const float* __restrict__ W_hh,
                            __nv_bfloat16* __restrict__ wc) {
    size_t i = (size_t)blockIdx.x * blockDim.x + threadIdx.x;
    if (i >= (size_t)G4H * KA) return;
    int r = (int)(i / KA), k = (int)(i % KA);
    float v = (k < E_) ? W_ih[(size_t)r * (2*E_) + E_ + k]
                       : W_hh[(size_t)r * H_ + (k - E_)];
    wc[i] = __float2bfloat16(v);
}

/* ---------------- embedding gather ---------------- */
__global__ void gather_emb(const float* __restrict__ emb_table,
                           const int* __restrict__ label,
                           float* __restrict__ emb) {
    int r = blockIdx.x;
    int n = label[r];
    const float* src = emb_table + (size_t)n * E_;
    float* dst = emb + (size_t)r * E_;
    for (int i = threadIdx.x; i < E_; i += blockDim.x) dst[i] = src[i];
}

/* ---------------- transpose (512,2048) -> (2048,512) ---------------- */
__global__ void transposeEH(const float* __restrict__ A, float* __restrict__ At) {
    __shared__ float tile[32][33];
    int x0 = blockIdx.x * 32, y0 = blockIdx.y * 32;
    int tx = threadIdx.x, ty = threadIdx.y;
    for (int j = 0; j < 32; j += 8)
        tile[ty+j][tx] = A[(size_t)(y0+ty+j) * H_ + x0 + tx];
    __syncthreads();
    for (int j = 0; j < 32; j += 8)
        At[(size_t)(x0+ty+j) * E_ + y0 + tx] = tile[tx][ty+j];
}

/* ============ tf32 tensor-core GEMM v3: 128x128 block, 32x64 warp tiles ============ */
#define TKC 32
#define TKP (TKC+4)
__global__ __launch_bounds__(256) void tgemm_tn(
        const float* __restrict__ W, int ldw,
        const float* __restrict__ X, int ldx,
        const float* __restrict__ bias,
        float* __restrict__ C, size_t ldcw, size_t ldcx,
        int M, int Nx, int K)
{
    __shared__ unsigned Ws[128][TKP];
    __shared__ unsigned Xs[128][TKP];
    int tid = threadIdx.x;
    int wid = tid >> 5, lane = tid & 31;
    int wm = (wid & 3) * 32;           /* warp M offset: 4 tiles */
    int wn = (wid >> 2) * 64;          /* warp N offset: 2 tiles of 64 */
    int m0 = blockIdx.y * 128;
    int n0 = blockIdx.x * 128;
    int g = lane >> 2, t = lane & 3;

    int srow = tid >> 1, scol = (tid & 1) * 16;   /* staging coords (both W and X) */

    float c[2][8][4];
#pragma unroll
    for (int i = 0; i < 2; i++)
#pragma unroll
        for (int j = 0; j < 8; j++)
#pragma unroll
            for (int q = 0; q < 4; q++) c[i][j][q] = 0.f;

    for (int k0 = 0; k0 < K; k0 += TKC) {
        /* stage W tile 128x32 */
#pragma unroll
        for (int i = 0; i < 4; i++) {
            float4 v = make_float4(0.f,0.f,0.f,0.f);
            if (m0 + srow < M)
                v = *(const float4*)(W + (size_t)(m0 + srow) * ldw + k0 + scol + i*4);
            Ws[srow][scol+i*4+0] = tf32c(v.x); Ws[srow][scol+i*4+1] = tf32c(v.y);
            Ws[srow][scol+i*4+2] = tf32c(v.z); Ws[srow][scol+i*4+3] = tf32c(v.w);
        }
        /* stage X tile 128x32 */
#pragma unroll
        for (int i = 0; i < 4; i++) {
            float4 v = make_float4(0.f,0.f,0.f,0.f);
            if (n0 + srow < Nx)
                v = *(const float4*)(X + (size_t)(n0 + srow) * ldx + k0 + scol + i*4);
            Xs[srow][scol+i*4+0] = tf32c(v.x); Xs[srow][scol+i*4+1] = tf32c(v.y);
            Xs[srow][scol+i*4+2] = tf32c(v.z); Xs[srow][scol+i*4+3] = tf32c(v.w);
        }
        __syncthreads();

#pragma unroll
        for (int kk = 0; kk < TKC; kk += 8) {
            unsigned a[2][4];
#pragma unroll
            for (int mt = 0; mt < 2; mt++) {
                int br = wm + mt*16;
                a[mt][0] = Ws[br + g    ][kk + t];
                a[mt][1] = Ws[br + g + 8][kk + t];
                a[mt][2] = Ws[br + g    ][kk + t + 4];
                a[mt][3] = Ws[br + g + 8][kk + t + 4];
            }
            unsigned b[8][2];
#pragma unroll
            for (int nt = 0; nt < 8; nt++) {
                b[nt][0] = Xs[wn + nt*8 + g][kk + t];
                b[nt][1] = Xs[wn + nt*8 + g][kk + t + 4];
            }
#pragma unroll
            for (int mt = 0; mt < 2; mt++)
#pragma unroll
                for (int nt = 0; nt < 8; nt++) {
                    asm volatile(
                        "mma.sync.aligned.m16n8k8.row.col.f32.tf32.tf32.f32 "
                        "{%0,%1,%2,%3}, {%4,%5,%6,%7}, {%8,%9}, {%0,%1,%2,%3};"
                        : "+f"(c[mt][nt][0]), "+f"(c[mt][nt][1]),
                          "+f"(c[mt][nt][2]), "+f"(c[mt][nt][3])
                        : "r"(a[mt][0]), "r"(a[mt][1]), "r"(a[mt][2]), "r"(a[mt][3]),
                          "r"(b[nt][0]), "r"(b[nt][1]));
                }
        }
        __syncthreads();
    }

#pragma unroll
    for (int mt = 0; mt < 2; mt++) {
#pragma unroll
        for (int nt = 0; nt < 8; nt++) {
            int row0 = m0 + wm + mt*16 + g;
            int col0 = n0 + wn + nt*8 + 2*t;
#pragma unroll
            for (int half = 0; half < 2; half++) {
                int row = row0 + half*8;
                if (row >= M) continue;
                float bv = bias ? bias[row] : 0.f;
                if (col0 < Nx)
                    C[(size_t)row*ldcw + (size_t)col0*ldcx] = c[mt][nt][half*2+0] + bv;
                if (col0 + 1 < Nx)
                    C[(size_t)row*ldcw + (size_t)(col0+1)*ldcx] = c[mt][nt][half*2+1] + bv;
            }
        }
    }
}

/* ================ PERSISTENT DECODER LOOP (unchanged from R12) ================ */
__global__ __launch_bounds__(NT) void decoder_loop(
        const float* __restrict__ x, const float* __restrict__ mask,
        const __nv_bfloat16* __restrict__ wcomb,
        const float* __restrict__ wproj, const float* __restrict__ comb,
        const float* __restrict__ eg,
        const float* __restrict__ v_m, const float* __restrict__ v_c,
        const float* __restrict__ r_m,
        const float* __restrict__ xh_m, const float* __restrict__ xh_c,
        float* gates, float* hb, float* cb, float* alb,
        __nv_bfloat16* actbf,
        float* smv, float* scv, float* pv, float* uvv, float* betav,
        float* scall)
{
    extern __shared__ char dyn[];
    __nv_bfloat16* sACT = (__nv_bfloat16*)dyn;
    __nv_bfloat16* sWT  = sACT + 16*APAD;
    float*         sPART = (float*)sWT;

    __shared__ float shA[T_], shB[T_], shC[T_], shD[T_], shR[T_];
    int tid = threadIdx.x;
    int lane = tid & 31;
    int wid = tid >> 5;
    int gw = blockIdx.x * (NT/32) + wid;
    int NW = gridDim.x * (NT/32);
    int gtid = blockIdx.x * NT + tid;
    int NTH = gridDim.x * NT;
    int g = lane >> 2, t = lane & 3;

    int n0 = blockIdx.x * 32;
    int nt = wid & 3;
    int khalf = wid >> 2;

    for (int u = 0; u < U_; u++) {
        float*       h_out = hb + ((u&1)^1)*(B_*H_);
        const float* c_in  = cb + (u&1)*(B_*H_);
        float*       c_out = cb + ((u&1)^1)*(B_*H_);
        const float* al_in  = alb + (u&1)*(T_*B_);
        float*       al_out = alb + ((u&1)^1)*(T_*B_);
        const float* eg_u = eg + (size_t)u*B_*G4H;
        float*       sc_u = scall + (size_t)u*B_*(2*E_);

        /* ---- Phase A: gates via smem-staged bf16 MMA ---- */
        for (int idx = tid; idx < 16*(KA/8); idx += NT) {
            int b = idx / (KA/8), f = idx % (KA/8);
            *(float4*)(sACT + (size_t)b*APAD + f*8) =
                *(const float4*)(actbf + (size_t)b*KA + f*8);
        }
        __syncthreads();

        float c0 = 0.f, c1 = 0.f, c2 = 0.f, c3 = 0.f;
        for (int it = 0; it < KHF/64; it++) {
            int kc = it * 64;
            for (int idx = tid; idx < 512; idx += NT) {
                int half = idx >> 8, row = (idx >> 3) & 31, f = idx & 7;
                *(float4*)(sWT + ((size_t)half*32 + row)*WPAD + f*8) =
                    *(const float4*)(wcomb + (size_t)(n0 + row)*KA + half*KHF + kc + f*8);
            }
            __syncthreads();

            const __nv_bfloat16* wrow = sWT + ((size_t)khalf*32 + nt*8 + g)*WPAD;
            const __nv_bfloat16* ar0 = sACT + (size_t)g*APAD + khalf*KHF + kc;
            const __nv_bfloat16* ar1 = sACT + (size_t)(g+8)*APAD + khalf*KHF + kc;
#pragma unroll
            for (int sub = 0; sub < 4; sub++) {
                int ks = sub*16;
                unsigned a0 = *(const unsigned*)(ar0 + ks + 2*t);
                unsigned a1 = *(const unsigned*)(ar1 + ks + 2*t);
                unsigned a2 = *(const unsigned*)(ar0 + ks + 2*t + 8);
                unsigned a3 = *(const unsigned*)(ar1 + ks + 2*t + 8);
                unsigned b0 = *(const unsigned*)(wrow + ks + 2*t);
                unsigned b1 = *(const unsigned*)(wrow + ks + 2*t + 8);
                asm volatile(
                    "mma.sync.aligned.m16n8k16.row.col.f32.bf16.bf16.f32 "
                    "{%0,%1,%2,%3}, {%4,%5,%6,%7}, {%8,%9}, {%0,%1,%2,%3};"
                    : "+f"(c0), "+f"(c1), "+f"(c2), "+f"(c3)
                    : "r"(a0), "r"(a1), "r"(a2), "r"(a3), "r"(b0), "r"(b1));
            }
            __syncthreads();
        }

        if (khalf == 1) {
            float* pp = sPART + (size_t)nt*128;
            pp[g*8 + 2*t]            = c0;
            pp[g*8 + 2*t + 1]        = c1;
            pp[(g+8)*8 + 2*t]        = c2;
            pp[(g+8)*8 + 2*t + 1]    = c3;
        }
        __syncthreads();
        if (khalf == 0) {
            const float* pp = sPART + (size_t)nt*128;
            int col0 = n0 + nt*8 + 2*t;
            gates[(size_t)g*G4H + col0]         = c0 + pp[g*8 + 2*t]         + eg_u[(size_t)g*G4H + col0];
            gates[(size_t)g*G4H + col0 + 1]     = c1 + pp[g*8 + 2*t + 1]     + eg_u[(size_t)g*G4H + col0 + 1];
            gates[(size_t)(g+8)*G4H + col0]     = c2 + pp[(g+8)*8 + 2*t]     + eg_u[(size_t)(g+8)*G4H + col0];
            gates[(size_t)(g+8)*G4H + col0 + 1] = c3 + pp[(g+8)*8 + 2*t + 1] + eg_u[(size_t)(g+8)*G4H + col0 + 1];
        }
        gbar();

        /* ---- Phase B: LSTM pointwise ---- */
        for (int i = gtid; i < B_*H_; i += NTH) {
            int b = i >> 11, k = i & (H_-1);
            const float* gp = gates + (size_t)b * G4H;
            float gi = gp[k], gf = gp[H_ + k], gg = gp[2*H_ + k], go = gp[3*H_ + k];
            float cn = sigm(gf) * c_in[i] + sigm(gi) * tanhf(gg);
            c_out[i] = cn;
            float hn = sigm(go) * tanhf(cn);
            h_out[i] = hn;
            actbf[(size_t)b * KA + E_ + k] = __float2bfloat16(hn);
        }
        gbar();

        /* ---- Phase C: s / sm / sc (fp32) ---- */
        for (int r = gw; r < 3*E_; r += NW) {
            const float* Wr = (r < E_) ? (wproj + (size_t)r * H_)
                                       : (comb + (size_t)(r - E_) * H_);
            float acc[16];
#pragma unroll
            for (int b = 0; b < 16; b++) acc[b] = 0.f;
            for (int k = lane*4; k < H_; k += 128) {
                float4 wv = *(const float4*)(Wr + k);
#pragma unroll
                for (int b = 0; b < 16; b++) {
                    float4 a = *(const float4*)(h_out + (size_t)b*H_ + k);
                    acc[b] += wv.x*a.x + wv.y*a.y + wv.z*a.z + wv.w*a.w;
                }
            }
#pragma unroll
            for (int b = 0; b < 16; b++)
#pragma unroll
                for (int off = 16; off > 0; off >>= 1)
                    acc[b] += __shfl_xor_sync(0xffffffffu, acc[b], off);
            if (lane < 16) {
                float v = acc[lane];
                if (r < E_)            sc_u[lane*(2*E_) + r] = v;
                else if (r < 2*E_)     smv[lane*E_ + (r - E_)] = v;
                else                   scv[lane*E_ + (r - 2*E_)] = v;
            }
        }
        gbar();

        /* ---- Phase D: energies ---- */
        for (int w = gw; w < T_*B_; w += NW) {
            int tt = w >> 4, b = w & 15;
            const float* xmp = xh_m + (size_t)(tt*B_ + b) * E_;
            const float* xcp = xh_c + (size_t)(tt*B_ + b) * E_;
            const float* smp = smv + (size_t)b * E_;
            const float* scp = scv + (size_t)b * E_;
            float am = 0.f, ac = 0.f;
            for (int e = lane*4; e < E_; e += 128) {
                float4 a  = *(const float4*)(xmp + e);
                float4 s4 = *(const float4*)(smp + e);
                float4 v4 = *(const float4*)(v_m + e);
                am += v4.x*tanha(a.x+s4.x) + v4.y*tanha(a.y+s4.y)
                    + v4.z*tanha(a.z+s4.z) + v4.w*tanha(a.w+s4.w);
                float4 a2  = *(const float4*)(xcp + e);
                float4 s42 = *(const float4*)(scp + e);
                float4 v42 = *(const float4*)(v_c + e);
                ac += v42.x*tanha(a2.x+s42.x) + v42.y*tanha(a2.y+s42.y)
                    + v42.z*tanha(a2.z+s42.z) + v42.w*tanha(a2.w+s42.w);
            }
#pragma unroll
            for (int off = 16; off > 0; off >>= 1) {
                am += __shfl_xor_sync(0xffffffffu, am, off);
                ac += __shfl_xor_sync(0xffffffffu, ac, off);
            }
            if (lane == 0) {
                float mk = mask[b*T_ + tt];
                pv[tt*B_ + b] = sigm(am + r_m[0]) * mk;
                uvv[tt*B_ + b] = ac;
            }
        }
        gbar();

        /* ---- Phase E: per-b scans ---- */
        if (blockIdx.x < B_) {
            int b = blockIdx.x, tt = tid;
            float pvv = pv[tt*B_ + b];
            float uvl = uvv[tt*B_ + b];
            float ap  = al_in[tt*B_ + b];
            float mk  = mask[b*T_ + tt];

            shR[tt] = uvl; __syncthreads();
            for (int off = 128; off > 0; off >>= 1) {
                if (tt < off) shR[tt] = fmaxf(shR[tt], shR[tt+off]);
                __syncthreads();
            }
            float um = shR[0];

            float eu = expf(uvl - um) * mk;
            shA[tt] = eu; __syncthreads();
#pragma unroll
            for (int off = 1; off < T_; off <<= 1) {
                float xv = (tt >= off) ? shA[tt-off] : 0.f;
                __syncthreads(); shA[tt] += xv; __syncthreads();
            }
            float denom = shA[tt] - (tt >= 8 ? shA[tt-8] : 0.f);

            shB[tt] = 1.f - pvv; __syncthreads();
#pragma unroll
            for (int off = 1; off < T_; off <<= 1) {
                float xv = (tt >= off) ? shB[tt-off] : 1.f;
                __syncthreads(); shB[tt] *= xv; __syncthreads();
            }
            float cp = (tt == 0) ? 1.f : shB[tt-1];

            shC[tt] = ap / fmaxf(cp, EPS_); __syncthreads();
#pragma unroll
            for (int off = 1; off < T_; off <<= 1) {
                float xv = (tt >= off) ? shC[tt-off] : 0.f;
                __syncthreads(); shC[tt] += xv; __syncthreads();
            }
            float av = pvv * cp * shC[tt];

            shD[tt] = av / fmaxf(denom, EPS_); __syncthreads();
#pragma unroll
            for (int off = 1; off < T_; off <<= 1) {
                float xv = (tt >= off) ? shD[tt-off] : 0.f;
                __syncthreads(); shD[tt] += xv; __syncthreads();
            }
            int hi = (tt + 7 > T_-1) ? (T_-1) : (tt + 7);
            float bv = eu * (shD[hi] - (tt > 0 ? shD[tt-1] : 0.f));

            al_out[tt*B_ + b] = av;
            betav[tt*B_ + b] = bv;
        }
        gbar();

        /* ---- Phase F: ctx -> scall + actbf ---- */
        for (int i = gtid; i < B_*E_; i += NTH) {
            int b = i >> 9, d = i & (E_-1);
            const float* xp = x + (size_t)b*E_ + d;
            float acc = 0.f;
#pragma unroll 8
            for (int tq = 0; tq < T_; tq++)
                acc += betav[tq*B_ + b] * xp[(size_t)tq * B_ * E_];
            sc_u[(size_t)b*(2*E_) + E_ + d] = acc;
            actbf[(size_t)b * KA + d] = __float2bfloat16(acc);
        }
        gbar();
    }
}

/* ---------------- host launcher ---------------- */
extern "C" void kernel_launch(void* const* d_in, const int* in_sizes, int n_in,
                              void* d_out, int out_size)
{
    const float* x        = (const float*)d_in[0];
    const float* att_mask = (const float*)d_in[1];
    const float* emb_tab  = (const float*)d_in[2];
    const float* W_ih     = (const float*)d_in[3];
    const float* W_hh     = (const float*)d_in[4];
    const float* b_lstm   = (const float*)d_in[5];
    const float* W_proj   = (const float*)d_in[6];
    const float* Ws_m     = (const float*)d_in[7];
    const float* Wh_m     = (const float*)d_in[8];
    const float* v_m      = (const float*)d_in[9];
    const float* r_m      = (const float*)d_in[10];
    const float* Ws_c     = (const float*)d_in[11];
    const float* Wh_c     = (const float*)d_in[12];
    const float* v_c      = (const float*)d_in[13];
    const float* W_am     = (const float*)d_in[14];
    const float* W_lm     = (const float*)d_in[15];
    const int*   label    = (const int*)d_in[16];

    float* out_am = (float*)d_out;
    float* out_lm = out_am + (size_t)N_ * U_ * B_;

    float *xh_m, *xh_c, *emb, *eg, *gates, *hb, *cb, *alb, *sm, *sc, *p, *uu, *beta, *scall, *wpT, *comb;
    __nv_bfloat16 *wcomb, *actbf;
    cudaGetSymbolAddress((void**)&xh_m,  g_xh_m);
    cudaGetSymbolAddress((void**)&xh_c,  g_xh_c);
    cudaGetSymbolAddress((void**)&emb,   g_emb);
    cudaGetSymbolAddress((void**)&eg,    g_eg);
    cudaGetSymbolAddress((void**)&gates, g_gates);
    cudaGetSymbolAddress((void**)&hb,    g_h);
    cudaGetSymbolAddress((void**)&cb,    g_c);
    cudaGetSymbolAddress((void**)&alb,   g_alpha);
    cudaGetSymbolAddress((void**)&sm,    g_sm);
    cudaGetSymbolAddress((void**)&sc,    g_sc);
    cudaGetSymbolAddress((void**)&p,     g_p);
    cudaGetSymbolAddress((void**)&uu,    g_u);
    cudaGetSymbolAddress((void**)&beta,  g_beta);
    cudaGetSymbolAddress((void**)&scall, g_scall);
    cudaGetSymbolAddress((void**)&wpT,   g_wpT);
    cudaGetSymbolAddress((void**)&comb,  g_comb);
    cudaGetSymbolAddress((void**)&wcomb, g_wcomb);
    cudaGetSymbolAddress((void**)&actbf, g_actbf);

    init_state<<<(2*B_*H_ + 255)/256, 256>>>(hb, cb, alb, actbf);

    {
        size_t n = (size_t)G4H * KA;
        build_wcomb<<<(int)((n + 511)/512), 512>>>(W_ih, W_hh, wcomb);
    }

    gather_emb<<<U_*B_, 128>>>(emb_tab, label, emb);

    /* encoder-side projections */
    tgemm_tn<<<dim3((T_*B_+127)/128, (E_+127)/128), 256>>>(Wh_m, E_, x, E_, nullptr,
            xh_m, 1, E_, E_, T_*B_, E_);
    tgemm_tn<<<dim3((T_*B_+127)/128, (E_+127)/128), 256>>>(Wh_c, E_, x, E_, nullptr,
            xh_c, 1, E_, E_, T_*B_, E_);

    /* eg = emb @ W_ih[:, :E]^T + b_lstm */
    tgemm_tn<<<dim3((U_*B_+127)/128, (G4H+127)/128), 256>>>(W_ih, 2*E_, emb, E_, b_lstm,
            eg, 1, G4H, G4H, U_*B_, E_);

    /* lm output */
    tgemm_tn<<<dim3((U_*B_+127)/128, (N_+127)/128), 256>>>(W_lm, E_, emb, E_, nullptr,
            out_lm, U_*B_, 1, N_, U_*B_, E_);

    /* folds: comb = [Ws_m@W_proj ; Ws_c@W_proj] */
    transposeEH<<<dim3(H_/32, E_/32), dim3(32, 8)>>>(W_proj, wpT);
    tgemm_tn<<<dim3((H_+127)/128, (E_+127)/128), 256>>>(Ws_m, E_, wpT, E_, nullptr,
            comb, H_, 1, E_, H_, E_);
    tgemm_tn<<<dim3((H_+127)/128, (E_+127)/128), 256>>>(Ws_c, E_, wpT, E_, nullptr,
            comb + (size_t)E_*H_, H_, 1, E_, H_, E_);

    /* 48-step recurrence in one persistent kernel */
    static int smem_set = 0;
    if (!smem_set) {
        cudaFuncSetAttribute(decoder_loop, cudaFuncAttributeMaxDynamicSharedMemorySize, SMEM_DYN);
        smem_set = 1;
    }
    decoder_loop<<<GRID, NT, SMEM_DYN>>>(x, att_mask, wcomb, W_proj, comb,
            eg, v_m, v_c, r_m, xh_m, xh_c,
            gates, hb, cb, alb, actbf,
            sm, sc, p, uu, beta, scall);

    /* am output */
    tgemm_tn<<<dim3((U_*B_+127)/128, (N_+127)/128), 256>>>(W_am, 2*E_, scall, 2*E_, nullptr,
            out_am, U_*B_, 1, N_, U_*B_, 2*E_);
}

// round 14
// speedup vs baseline: 1.5485x; 1.0005x over previous
#include <cuda_runtime.h>
#include <cuda_bf16.h>
#include <math.h>

#define T_ 256
#define B_ 16
#define E_ 512
#define H_ 2048
#define N_ 14839
#define U_ 48
#define G4H 8192
#define KA 2560
#define KHF 1280
#define EPS_ 1e-6f
#define NT 256
#define GRID 256
#define APAD 2568
#define WPAD 72
#define SMEM_DYN ((16*APAD + 2*32*WPAD) * 2)

/* ---------------- scratch ---------------- */
__device__ float g_xh_m[T_*B_*E_];
__device__ float g_xh_c[T_*B_*E_];
__device__ float g_emb[U_*B_*E_];
__device__ float g_eg[(size_t)U_*B_*G4H];
__device__ float g_gates[(size_t)B_*G4H];
__device__ float g_h[2][B_*H_];
__device__ float g_c[2][B_*H_];
__device__ float g_alpha[2][T_*B_];
__device__ float g_sm[B_*E_];
__device__ float g_sc[B_*E_];
__device__ float g_p[T_*B_];
__device__ float g_u[T_*B_];
__device__ float g_beta[T_*B_];
__device__ float g_scall[U_*B_*2*E_];
__device__ float g_wpT[H_*E_];
__device__ float g_comb[2*E_*H_];
__device__ __nv_bfloat16 g_wcomb[(size_t)G4H*KA];
__device__ __nv_bfloat16 g_actbf[B_*KA];

/* grid barrier state */
__device__ unsigned g_cnt = 0;
__device__ volatile unsigned g_gen = 0;

__device__ __forceinline__ void gbar() {
    __syncthreads();
    if (threadIdx.x == 0) {
        unsigned gen = g_gen;
        __threadfence();
        if (atomicAdd(&g_cnt, 1u) == gridDim.x - 1u) {
            g_cnt = 0;
            __threadfence();
            g_gen = gen + 1u;
        } else {
            while (g_gen == gen) __nanosleep(32);
        }
        __threadfence();
    }
    __syncthreads();
}

__device__ __forceinline__ float sigm(float x) { return 1.f / (1.f + expf(-x)); }
__device__ __forceinline__ unsigned tf32c(float x) {
    unsigned r; asm("cvt.rna.tf32.f32 %0, %1;" : "=r"(r) : "f"(x)); return r;
}
/* paired fp16 tanh: 2 elements per MUFU op */
__device__ __forceinline__ float2 tanh2(float e0, float e1) {
    unsigned pk;
    asm("cvt.rn.f16x2.f32 %0, %1, %2;" : "=r"(pk) : "f"(e1), "f"(e0)); /* e0->lo, e1->hi */
    asm("tanh.approx.f16x2 %0, %0;" : "+r"(pk));
    float t0, t1;
    asm("{.reg .f16 lo, hi;\n\t"
        "mov.b32 {lo, hi}, %2;\n\t"
        "cvt.f32.f16 %0, lo;\n\t"
        "cvt.f32.f16 %1, hi;}"
        : "=f"(t0), "=f"(t1) : "r"(pk));
    return make_float2(t0, t1);
}

/* ---------------- init ---------------- */
__global__ void init_state(float* h, float* c, float* alpha, __nv_bfloat16* actbf) {
    int i = blockIdx.x * blockDim.x + threadIdx.x;
    if (i < 2*B_*H_) { h[i] = 0.f; c[i] = 0.f; }
    if (i < B_*KA)   actbf[i] = __float2bfloat16(0.f);
    if (i < T_*B_)   alpha[i] = (i < B_) ? 1.f : 0.f;
}

/* ---------------- combined bf16 weight build ---------------- */
__global__ void build_wcomb(const float* __restrict__ W_ih, const float* __restrict__ W_hh,
                            __nv_bfloat16* __restrict__ wc) {
    size_t i = (size_t)blockIdx.x * blockDim.x + threadIdx.x;
    if (i >= (size_t)G4H * KA) return;
    int r = (int)(i / KA), k = (int)(i % KA);
    float v = (k < E_) ? W_ih[(size_t)r * (2*E_) + E_ + k]
                       : W_hh[(size_t)r * H_ + (k - E_)];
    wc[i] = __float2bfloat16(v);
}

/* ---------------- embedding gather ---------------- */
__global__ void gather_emb(const float* __restrict__ emb_table,
                           const int* __restrict__ label,
                           float* __restrict__ emb) {
    int r = blockIdx.x;
    int n = label[r];
    const float* src = emb_table + (size_t)n * E_;
    float* dst = emb + (size_t)r * E_;
    for (int i = threadIdx.x; i < E_; i += blockDim.x) dst[i] = src[i];
}

/* ---------------- transpose (512,2048) -> (2048,512) ---------------- */
__global__ void transposeEH(const float* __restrict__ A, float* __restrict__ At) {
    __shared__ float tile[32][33];
    int x0 = blockIdx.x * 32, y0 = blockIdx.y * 32;
    int tx = threadIdx.x, ty = threadIdx.y;
    for (int j = 0; j < 32; j += 8)
        tile[ty+j][tx] = A[(size_t)(y0+ty+j) * H_ + x0 + tx];
    __syncthreads();
    for (int j = 0; j < 32; j += 8)
        At[(size_t)(x0+ty+j) * E_ + y0 + tx] = tile[tx][ty+j];
}

/* ============ tf32 tensor-core GEMM v3: 128x128 block, 32x64 warp tiles ============ */
#define TKC 32
#define TKP (TKC+4)
__global__ __launch_bounds__(256) void tgemm_tn(
        const float* __restrict__ W, int ldw,
        const float* __restrict__ X, int ldx,
        const float* __restrict__ bias,
        float* __restrict__ C, size_t ldcw, size_t ldcx,
        int M, int Nx, int K)
{
    __shared__ unsigned Ws[128][TKP];
    __shared__ unsigned Xs[128][TKP];
    int tid = threadIdx.x;
    int wid = tid >> 5, lane = tid & 31;
    int wm = (wid & 3) * 32;
    int wn = (wid >> 2) * 64;
    int m0 = blockIdx.y * 128;
    int n0 = blockIdx.x * 128;
    int g = lane >> 2, t = lane & 3;

    int srow = tid >> 1, scol = (tid & 1) * 16;

    float c[2][8][4];
#pragma unroll
    for (int i = 0; i < 2; i++)
#pragma unroll
        for (int j = 0; j < 8; j++)
#pragma unroll
            for (int q = 0; q < 4; q++) c[i][j][q] = 0.f;

    for (int k0 = 0; k0 < K; k0 += TKC) {
#pragma unroll
        for (int i = 0; i < 4; i++) {
            float4 v = make_float4(0.f,0.f,0.f,0.f);
            if (m0 + srow < M)
                v = *(const float4*)(W + (size_t)(m0 + srow) * ldw + k0 + scol + i*4);
            Ws[srow][scol+i*4+0] = tf32c(v.x); Ws[srow][scol+i*4+1] = tf32c(v.y);
            Ws[srow][scol+i*4+2] = tf32c(v.z); Ws[srow][scol+i*4+3] = tf32c(v.w);
        }
#pragma unroll
        for (int i = 0; i < 4; i++) {
            float4 v = make_float4(0.f,0.f,0.f,0.f);
            if (n0 + srow < Nx)
                v = *(const float4*)(X + (size_t)(n0 + srow) * ldx + k0 + scol + i*4);
            Xs[srow][scol+i*4+0] = tf32c(v.x); Xs[srow][scol+i*4+1] = tf32c(v.y);
            Xs[srow][scol+i*4+2] = tf32c(v.z); Xs[srow][scol+i*4+3] = tf32c(v.w);
        }
        __syncthreads();

#pragma unroll
        for (int kk = 0; kk < TKC; kk += 8) {
            unsigned a[2][4];
#pragma unroll
            for (int mt = 0; mt < 2; mt++) {
                int br = wm + mt*16;
                a[mt][0] = Ws[br + g    ][kk + t];
                a[mt][1] = Ws[br + g + 8][kk + t];
                a[mt][2] = Ws[br + g    ][kk + t + 4];
                a[mt][3] = Ws[br + g + 8][kk + t + 4];
            }
            unsigned b[8][2];
#pragma unroll
            for (int nt = 0; nt < 8; nt++) {
                b[nt][0] = Xs[wn + nt*8 + g][kk + t];
                b[nt][1] = Xs[wn + nt*8 + g][kk + t + 4];
            }
#pragma unroll
            for (int mt = 0; mt < 2; mt++)
#pragma unroll
                for (int nt = 0; nt < 8; nt++) {
                    asm volatile(
                        "mma.sync.aligned.m16n8k8.row.col.f32.tf32.tf32.f32 "
                        "{%0,%1,%2,%3}, {%4,%5,%6,%7}, {%8,%9}, {%0,%1,%2,%3};"
                        : "+f"(c[mt][nt][0]), "+f"(c[mt][nt][1]),
                          "+f"(c[mt][nt][2]), "+f"(c[mt][nt][3])
                        : "r"(a[mt][0]), "r"(a[mt][1]), "r"(a[mt][2]), "r"(a[mt][3]),
                          "r"(b[nt][0]), "r"(b[nt][1]));
                }
        }
        __syncthreads();
    }

#pragma unroll
    for (int mt = 0; mt < 2; mt++) {
#pragma unroll
        for (int nt = 0; nt < 8; nt++) {
            int row0 = m0 + wm + mt*16 + g;
            int col0 = n0 + wn + nt*8 + 2*t;
#pragma unroll
            for (int half = 0; half < 2; half++) {
                int row = row0 + half*8;
                if (row >= M) continue;
                float bv = bias ? bias[row] : 0.f;
                if (col0 < Nx)
                    C[(size_t)row*ldcw + (size_t)col0*ldcx] = c[mt][nt][half*2+0] + bv;
                if (col0 + 1 < Nx)
                    C[(size_t)row*ldcw + (size_t)(col0+1)*ldcx] = c[mt][nt][half*2+1] + bv;
            }
        }
    }
}

/* ================ PERSISTENT DECODER LOOP ================ */
__global__ __launch_bounds__(NT) void decoder_loop(
        const float* __restrict__ x, const float* __restrict__ mask,
        const __nv_bfloat16* __restrict__ wcomb,
        const float* __restrict__ wproj, const float* __restrict__ comb,
        const float* __restrict__ eg,
        const float* __restrict__ v_m, const float* __restrict__ v_c,
        const float* __restrict__ r_m,
        const float* __restrict__ xh_m, const float* __restrict__ xh_c,
        float* gates, float* hb, float* cb, float* alb,
        __nv_bfloat16* actbf,
        float* smv, float* scv, float* pv, float* uvv, float* betav,
        float* scall)
{
    extern __shared__ char dyn[];
    __nv_bfloat16* sACT = (__nv_bfloat16*)dyn;
    __nv_bfloat16* sWT  = sACT + 16*APAD;
    float*         sPART = (float*)sWT;

    __shared__ float shA[T_], shB[T_], shC[T_], shD[T_], shR[T_];
    int tid = threadIdx.x;
    int lane = tid & 31;
    int wid = tid >> 5;
    int gw = blockIdx.x * (NT/32) + wid;
    int NW = gridDim.x * (NT/32);
    int gtid = blockIdx.x * NT + tid;
    int NTH = gridDim.x * NT;
    int g = lane >> 2, t = lane & 3;

    int n0 = blockIdx.x * 32;
    int nt = wid & 3;
    int khalf = wid >> 2;

    for (int u = 0; u < U_; u++) {
        float*       h_out = hb + ((u&1)^1)*(B_*H_);
        const float* c_in  = cb + (u&1)*(B_*H_);
        float*       c_out = cb + ((u&1)^1)*(B_*H_);
        const float* al_in  = alb + (u&1)*(T_*B_);
        float*       al_out = alb + ((u&1)^1)*(T_*B_);
        const float* eg_u = eg + (size_t)u*B_*G4H;
        float*       sc_u = scall + (size_t)u*B_*(2*E_);

        /* ---- Phase A: gates via smem-staged bf16 MMA ---- */
        for (int idx = tid; idx < 16*(KA/8); idx += NT) {
            int b = idx / (KA/8), f = idx % (KA/8);
            *(float4*)(sACT + (size_t)b*APAD + f*8) =
                *(const float4*)(actbf + (size_t)b*KA + f*8);
        }
        __syncthreads();

        float c0 = 0.f, c1 = 0.f, c2 = 0.f, c3 = 0.f;
        for (int it = 0; it < KHF/64; it++) {
            int kc = it * 64;
            for (int idx = tid; idx < 512; idx += NT) {
                int half = idx >> 8, row = (idx >> 3) & 31, f = idx & 7;
                *(float4*)(sWT + ((size_t)half*32 + row)*WPAD + f*8) =
                    *(const float4*)(wcomb + (size_t)(n0 + row)*KA + half*KHF + kc + f*8);
            }
            __syncthreads();

            const __nv_bfloat16* wrow = sWT + ((size_t)khalf*32 + nt*8 + g)*WPAD;
            const __nv_bfloat16* ar0 = sACT + (size_t)g*APAD + khalf*KHF + kc;
            const __nv_bfloat16* ar1 = sACT + (size_t)(g+8)*APAD + khalf*KHF + kc;
#pragma unroll
            for (int sub = 0; sub < 4; sub++) {
                int ks = sub*16;
                unsigned a0 = *(const unsigned*)(ar0 + ks + 2*t);
                unsigned a1 = *(const unsigned*)(ar1 + ks + 2*t);
                unsigned a2 = *(const unsigned*)(ar0 + ks + 2*t + 8);
                unsigned a3 = *(const unsigned*)(ar1 + ks + 2*t + 8);
                unsigned b0 = *(const unsigned*)(wrow + ks + 2*t);
                unsigned b1 = *(const unsigned*)(wrow + ks + 2*t + 8);
                asm volatile(
                    "mma.sync.aligned.m16n8k16.row.col.f32.bf16.bf16.f32 "
                    "{%0,%1,%2,%3}, {%4,%5,%6,%7}, {%8,%9}, {%0,%1,%2,%3};"
                    : "+f"(c0), "+f"(c1), "+f"(c2), "+f"(c3)
                    : "r"(a0), "r"(a1), "r"(a2), "r"(a3), "r"(b0), "r"(b1));
            }
            __syncthreads();
        }

        if (khalf == 1) {
            float* pp = sPART + (size_t)nt*128;
            pp[g*8 + 2*t]            = c0;
            pp[g*8 + 2*t + 1]        = c1;
            pp[(g+8)*8 + 2*t]        = c2;
            pp[(g+8)*8 + 2*t + 1]    = c3;
        }
        __syncthreads();
        if (khalf == 0) {
            const float* pp = sPART + (size_t)nt*128;
            int col0 = n0 + nt*8 + 2*t;
            gates[(size_t)g*G4H + col0]         = c0 + pp[g*8 + 2*t]         + eg_u[(size_t)g*G4H + col0];
            gates[(size_t)g*G4H + col0 + 1]     = c1 + pp[g*8 + 2*t + 1]     + eg_u[(size_t)g*G4H + col0 + 1];
            gates[(size_t)(g+8)*G4H + col0]     = c2 + pp[(g+8)*8 + 2*t]     + eg_u[(size_t)(g+8)*G4H + col0];
            gates[(size_t)(g+8)*G4H + col0 + 1] = c3 + pp[(g+8)*8 + 2*t + 1] + eg_u[(size_t)(g+8)*G4H + col0 + 1];
        }
        gbar();

        /* ---- Phase B: LSTM pointwise ---- */
        for (int i = gtid; i < B_*H_; i += NTH) {
            int b = i >> 11, k = i & (H_-1);
            const float* gp = gates + (size_t)b * G4H;
            float gi = gp[k], gf = gp[H_ + k], gg = gp[2*H_ + k], go = gp[3*H_ + k];
            float cn = sigm(gf) * c_in[i] + sigm(gi) * tanhf(gg);
            c_out[i] = cn;
            float hn = sigm(go) * tanhf(cn);
            h_out[i] = hn;
            actbf[(size_t)b * KA + E_ + k] = __float2bfloat16(hn);
        }
        gbar();

        /* ---- Phase C: s / sm / sc (fp32) ---- */
        for (int r = gw; r < 3*E_; r += NW) {
            const float* Wr = (r < E_) ? (wproj + (size_t)r * H_)
                                       : (comb + (size_t)(r - E_) * H_);
            float acc[16];
#pragma unroll
            for (int b = 0; b < 16; b++) acc[b] = 0.f;
            for (int k = lane*4; k < H_; k += 128) {
                float4 wv = *(const float4*)(Wr + k);
#pragma unroll
                for (int b = 0; b < 16; b++) {
                    float4 a = *(const float4*)(h_out + (size_t)b*H_ + k);
                    acc[b] += wv.x*a.x + wv.y*a.y + wv.z*a.z + wv.w*a.w;
                }
            }
#pragma unroll
            for (int b = 0; b < 16; b++)
#pragma unroll
                for (int off = 16; off > 0; off >>= 1)
                    acc[b] += __shfl_xor_sync(0xffffffffu, acc[b], off);
            if (lane < 16) {
                float v = acc[lane];
                if (r < E_)            sc_u[lane*(2*E_) + r] = v;
                else if (r < 2*E_)     smv[lane*E_ + (r - E_)] = v;
                else                   scv[lane*E_ + (r - 2*E_)] = v;
            }
        }
        gbar();

        /* ---- Phase D: energies (paired f16 tanh: 2 elems per MUFU) ---- */
        for (int w = gw; w < T_*B_; w += NW) {
            int tt = w >> 4, b = w & 15;
            const float* xmp = xh_m + (size_t)(tt*B_ + b) * E_;
            const float* xcp = xh_c + (size_t)(tt*B_ + b) * E_;
            const float* smp = smv + (size_t)b * E_;
            const float* scp = scv + (size_t)b * E_;
            float am = 0.f, ac = 0.f;
            for (int e = lane*4; e < E_; e += 128) {
                float4 a  = *(const float4*)(xmp + e);
                float4 s4 = *(const float4*)(smp + e);
                float4 v4 = *(const float4*)(v_m + e);
                float2 t01 = tanh2(a.x + s4.x, a.y + s4.y);
                float2 t23 = tanh2(a.z + s4.z, a.w + s4.w);
                am += v4.x*t01.x + v4.y*t01.y + v4.z*t23.x + v4.w*t23.y;

                float4 a2  = *(const float4*)(xcp + e);
                float4 s42 = *(const float4*)(scp + e);
                float4 v42 = *(const float4*)(v_c + e);
                float2 u01 = tanh2(a2.x + s42.x, a2.y + s42.y);
                float2 u23 = tanh2(a2.z + s42.z, a2.w + s42.w);
                ac += v42.x*u01.x + v42.y*u01.y + v42.z*u23.x + v42.w*u23.y;
            }
#pragma unroll
            for (int off = 16; off > 0; off >>= 1) {
                am += __shfl_xor_sync(0xffffffffu, am, off);
                ac += __shfl_xor_sync(0xffffffffu, ac, off);
            }
            if (lane == 0) {
                float mk = mask[b*T_ + tt];
                pv[tt*B_ + b] = sigm(am + r_m[0]) * mk;
                uvv[tt*B_ + b] = ac;
            }
        }
        gbar();

        /* ---- Phase E: per-b scans ---- */
        if (blockIdx.x < B_) {
            int b = blockIdx.x, tt = tid;
            float pvv = pv[tt*B_ + b];
            float uvl = uvv[tt*B_ + b];
            float ap  = al_in[tt*B_ + b];
            float mk  = mask[b*T_ + tt];

            shR[tt] = uvl; __syncthreads();
            for (int off = 128; off > 0; off >>= 1) {
                if (tt < off) shR[tt] = fmaxf(shR[tt], shR[tt+off]);
                __syncthreads();
            }
            float um = shR[0];

            float eu = expf(uvl - um) * mk;
            shA[tt] = eu; __syncthreads();
#pragma unroll
            for (int off = 1; off < T_; off <<= 1) {
                float xv = (tt >= off) ? shA[tt-off] : 0.f;
                __syncthreads(); shA[tt] += xv; __syncthreads();
            }
            float denom = shA[tt] - (tt >= 8 ? shA[tt-8] : 0.f);

            shB[tt] = 1.f - pvv; __syncthreads();
#pragma unroll
            for (int off = 1; off < T_; off <<= 1) {
                float xv = (tt >= off) ? shB[tt-off] : 1.f;
                __syncthreads(); shB[tt] *= xv; __syncthreads();
            }
            float cp = (tt == 0) ? 1.f : shB[tt-1];

            shC[tt] = ap / fmaxf(cp, EPS_); __syncthreads();
#pragma unroll
            for (int off = 1; off < T_; off <<= 1) {
                float xv = (tt >= off) ? shC[tt-off] : 0.f;
                __syncthreads(); shC[tt] += xv; __syncthreads();
            }
            float av = pvv * cp * shC[tt];

            shD[tt] = av / fmaxf(denom, EPS_); __syncthreads();
#pragma unroll
            for (int off = 1; off < T_; off <<= 1) {
                float xv = (tt >= off) ? shD[tt-off] : 0.f;
                __syncthreads(); shD[tt] += xv; __syncthreads();
            }
            int hi = (tt + 7 > T_-1) ? (T_-1) : (tt + 7);
            float bv = eu * (shD[hi] - (tt > 0 ? shD[tt-1] : 0.f));

            al_out[tt*B_ + b] = av;
            betav[tt*B_ + b] = bv;
        }
        gbar();

        /* ---- Phase F: ctx -> scall + actbf ---- */
        for (int i = gtid; i < B_*E_; i += NTH) {
            int b = i >> 9, d = i & (E_-1);
            const float* xp = x + (size_t)b*E_ + d;
            float acc = 0.f;
#pragma unroll 8
            for (int tq = 0; tq < T_; tq++)
                acc += betav[tq*B_ + b] * xp[(size_t)tq * B_ * E_];
            sc_u[(size_t)b*(2*E_) + E_ + d] = acc;
            actbf[(size_t)b * KA + d] = __float2bfloat16(acc);
        }
        gbar();
    }
}

/* ---------------- host launcher ---------------- */
extern "C" void kernel_launch(void* const* d_in, const int* in_sizes, int n_in,
                              void* d_out, int out_size)
{
    const float* x        = (const float*)d_in[0];
    const float* att_mask = (const float*)d_in[1];
    const float* emb_tab  = (const float*)d_in[2];
    const float* W_ih     = (const float*)d_in[3];
    const float* W_hh     = (const float*)d_in[4];
    const float* b_lstm   = (const float*)d_in[5];
    const float* W_proj   = (const float*)d_in[6];
    const float* Ws_m     = (const float*)d_in[7];
    const float* Wh_m     = (const float*)d_in[8];
    const float* v_m      = (const float*)d_in[9];
    const float* r_m      = (const float*)d_in[10];
    const float* Ws_c     = (const float*)d_in[11];
    const float* Wh_c     = (const float*)d_in[12];
    const float* v_c      = (const float*)d_in[13];
    const float* W_am     = (const float*)d_in[14];
    const float* W_lm     = (const float*)d_in[15];
    const int*   label    = (const int*)d_in[16];

    float* out_am = (float*)d_out;
    float* out_lm = out_am + (size_t)N_ * U_ * B_;

    float *xh_m, *xh_c, *emb, *eg, *gates, *hb, *cb, *alb, *sm, *sc, *p, *uu, *beta, *scall, *wpT, *comb;
    __nv_bfloat16 *wcomb, *actbf;
    cudaGetSymbolAddress((void**)&xh_m,  g_xh_m);
    cudaGetSymbolAddress((void**)&xh_c,  g_xh_c);
    cudaGetSymbolAddress((void**)&emb,   g_emb);
    cudaGetSymbolAddress((void**)&eg,    g_eg);
    cudaGetSymbolAddress((void**)&gates, g_gates);
    cudaGetSymbolAddress((void**)&hb,    g_h);
    cudaGetSymbolAddress((void**)&cb,    g_c);
    cudaGetSymbolAddress((void**)&alb,   g_alpha);
    cudaGetSymbolAddress((void**)&sm,    g_sm);
    cudaGetSymbolAddress((void**)&sc,    g_sc);
    cudaGetSymbolAddress((void**)&p,     g_p);
    cudaGetSymbolAddress((void**)&uu,    g_u);
    cudaGetSymbolAddress((void**)&beta,  g_beta);
    cudaGetSymbolAddress((void**)&scall, g_scall);
    cudaGetSymbolAddress((void**)&wpT,   g_wpT);
    cudaGetSymbolAddress((void**)&comb,  g_comb);
    cudaGetSymbolAddress((void**)&wcomb, g_wcomb);
    cudaGetSymbolAddress((void**)&actbf, g_actbf);

    init_state<<<(2*B_*H_ + 255)/256, 256>>>(hb, cb, alb, actbf);

    {
        size_t n = (size_t)G4H * KA;
        build_wcomb<<<(int)((n + 511)/512), 512>>>(W_ih, W_hh, wcomb);
    }

    gather_emb<<<U_*B_, 128>>>(emb_tab, label, emb);

    /* encoder-side projections */
    tgemm_tn<<<dim3((T_*B_+127)/128, (E_+127)/128), 256>>>(Wh_m, E_, x, E_, nullptr,
            xh_m, 1, E_, E_, T_*B_, E_);
    tgemm_tn<<<dim3((T_*B_+127)/128, (E_+127)/128), 256>>>(Wh_c, E_, x, E_, nullptr,
            xh_c, 1, E_, E_, T_*B_, E_);

    /* eg = emb @ W_ih[:, :E]^T + b_lstm */
    tgemm_tn<<<dim3((U_*B_+127)/128, (G4H+127)/128), 256>>>(W_ih, 2*E_, emb, E_, b_lstm,
            eg, 1, G4H, G4H, U_*B_, E_);

    /* lm output */
    tgemm_tn<<<dim3((U_*B_+127)/128, (N_+127)/128), 256>>>(W_lm, E_, emb, E_, nullptr,
            out_lm, U_*B_, 1, N_, U_*B_, E_);

    /* folds: comb = [Ws_m@W_proj ; Ws_c@W_proj] */
    transposeEH<<<dim3(H_/32, E_/32), dim3(32, 8)>>>(W_proj, wpT);
    tgemm_tn<<<dim3((H_+127)/128, (E_+127)/128), 256>>>(Ws_m, E_, wpT, E_, nullptr,
            comb, H_, 1, E_, H_, E_);
    tgemm_tn<<<dim3((H_+127)/128, (E_+127)/128), 256>>>(Ws_c, E_, wpT, E_, nullptr,
            comb + (size_t)E_*H_, H_, 1, E_, H_, E_);

    /* 48-step recurrence in one persistent kernel */
    static int smem_set = 0;
    if (!smem_set) {
        cudaFuncSetAttribute(decoder_loop, cudaFuncAttributeMaxDynamicSharedMemorySize, SMEM_DYN);
        smem_set = 1;
    }
    decoder_loop<<<GRID, NT, SMEM_DYN>>>(x, att_mask, wcomb, W_proj, comb,
            eg, v_m, v_c, r_m, xh_m, xh_c,
            gates, hb, cb, alb, actbf,
            sm, sc, p, uu, beta, scall);

    /* am output */
    tgemm_tn<<<dim3((U_*B_+127)/128, (N_+127)/128), 256>>>(W_am, 2*E_, scall, 2*E_, nullptr,
            out_am, U_*B_, 1, N_, U_*B_, 2*E_);
}